// round 3
// baseline (speedup 1.0000x reference)
#include <cuda_runtime.h>
#include <math.h>

#define NPTS   524288
#define HDIM   256
#define NCELL  32
#define DTH    31
#define EPSF   1e-7f
#define TINYF  1e-10f

// ---------------- device scratch (no cudaMalloc allowed) ----------------
__device__ float g_u[HDIM];
__device__ float g_c[HDIM];
__device__ float g_M[HDIM * 64];     // w3 @ B^T   [256][64]
__device__ float g_m0[64];           // b3 @ B^T
__device__ float g_H2[NPTS * HDIM];  // 512 MB
__device__ float g_A[NPTS * 64];     // 128 MB

// ============================================================================
// k0: reproduce numpy's SVD null-space basis B = Vt[33:].T via Householder LQ
//     (LAPACK dgesdd Path 4t: dgelqf + dorglq; rows 33..63 of Q are exactly
//      Vt[33:]), then fold constants: u,c (layers 0+1 collapse), M = w3@B^T,
//      m0 = b3@B^T. One block, fp64 for the factorization.
// ============================================================================
__global__ void k0_prep(const float* __restrict__ w0, const float* __restrict__ b0,
                        const float* __restrict__ w1, const float* __restrict__ b1,
                        const float* __restrict__ w3, const float* __restrict__ b3)
{
    __shared__ double sL[33][64];
    __shared__ double sB[31][64];
    __shared__ double sTau[33];
    const int tid = threadIdx.x;

    // Build constraint matrix L (33 x 64)
    for (int idx = tid; idx < 33 * 64; idx += blockDim.x)
        ((double*)sL)[idx] = 0.0;
    __syncthreads();
    if (tid == 0) {
        for (int i = 1; i < NCELL; i++) {
            double xi = (double)i / (double)NCELL;
            sL[i - 1][2 * (i - 1)]     = xi;
            sL[i - 1][2 * (i - 1) + 1] = 1.0;
            sL[i - 1][2 * i]           = -xi;
            sL[i - 1][2 * i + 1]       = -1.0;
        }
        sL[NCELL - 1][1]               = 1.0;
        sL[NCELL][2 * (NCELL - 1)]     = 1.0;
        sL[NCELL][2 * (NCELL - 1) + 1] = 1.0;
    }
    __syncthreads();

    // Householder LQ (dgelq2 semantics): for each row i, reflector over cols i..63
    for (int i = 0; i < 33; i++) {
        if (tid == 0) {
            double alpha = sL[i][i];
            double xn2 = 0.0;
            for (int j = i + 1; j < 64; j++) xn2 += sL[i][j] * sL[i][j];
            if (xn2 == 0.0) {
                sTau[i] = 0.0;
            } else {
                double beta = sqrt(alpha * alpha + xn2);
                beta = (alpha >= 0.0) ? -beta : beta;   // beta = -sign(alpha)*norm
                sTau[i] = (beta - alpha) / beta;
                double sc = 1.0 / (alpha - beta);
                for (int j = i + 1; j < 64; j++) sL[i][j] *= sc;
                sL[i][i] = beta;
            }
        }
        __syncthreads();
        double tau = sTau[i];
        if (tau != 0.0) {
            int r = i + 1 + tid;
            if (r < 33) {
                double w = sL[r][i];
                for (int j = i + 1; j < 64; j++) w += sL[r][j] * sL[i][j];
                w *= tau;
                sL[r][i] -= w;
                for (int j = i + 1; j < 64; j++) sL[r][j] -= w * sL[i][j];
            }
        }
        __syncthreads();
    }

    // Rows 33..63 of Q: start from E = [0 | I_31], apply H(32)..H(0) on the right
    for (int idx = tid; idx < 31 * 64; idx += blockDim.x)
        ((double*)sB)[idx] = 0.0;
    __syncthreads();
    if (tid < 31) sB[tid][33 + tid] = 1.0;
    __syncthreads();
    for (int i = 32; i >= 0; i--) {
        double tau = sTau[i];
        if (tau != 0.0 && tid < 31) {
            int r = tid;
            double w = sB[r][i];
            for (int j = i + 1; j < 64; j++) w += sB[r][j] * sL[i][j];
            w *= tau;
            sB[r][i] -= w;
            for (int j = i + 1; j < 64; j++) sB[r][j] -= w * sL[i][j];
        }
        __syncthreads();
    }
    // sB[d][j64] == B[j64][d]  (B = Vt[33:].T)

    // u[j] = sum_k w0[k] w1[k][j];  c[j] = sum_k b0[k] w1[k][j] + b1[j]
    if (tid < HDIM) {
        float uu = 0.f, cc = 0.f;
        for (int k = 0; k < HDIM; k++) {
            float wv = w1[k * HDIM + tid];
            uu = fmaf(w0[k], wv, uu);
            cc = fmaf(b0[k], wv, cc);
        }
        g_u[tid] = uu;
        g_c[tid] = cc + b1[tid];
    }
    // M[k][j64] = sum_d w3[k][d] * B[j64][d];  m0[j64] = sum_d b3[d] * B[j64][d]
    for (int idx = tid; idx < HDIM * 64; idx += blockDim.x) {
        int k = idx >> 6, j = idx & 63;
        float s = 0.f;
        for (int d = 0; d < DTH; d++)
            s = fmaf(w3[k * DTH + d], (float)sB[d][j], s);
        g_M[idx] = s;
    }
    if (tid < 64) {
        float s = 0.f;
        for (int d = 0; d < DTH; d++)
            s = fmaf(b3[d], (float)sB[d][tid], s);
        g_m0[tid] = s;
    }
}

// ============================================================================
// k1: H2 = relu( relu(x1*u + c) @ w2 + b2 )  -> g_H2 [N][256]
//     128x128 block tile, BK=16, 8x8 microtile, h1 recomputed on the fly.
// ============================================================================
__global__ void __launch_bounds__(256) k1_mlp(const float* __restrict__ x,
                                              const float* __restrict__ w2,
                                              const float* __restrict__ b2, int n)
{
    __shared__ float As[16][128];   // h1^T tile  [k][i]
    __shared__ float Bs[16][128];   // w2 tile    [k][j]
    __shared__ float xs[128];
    __shared__ float us[HDIM], cs[HDIM];

    const int i0 = blockIdx.x * 128;
    const int j0 = blockIdx.y * 128;
    const int tid = threadIdx.x;

    us[tid] = g_u[tid];
    cs[tid] = g_c[tid];
    if (tid < 128) {
        int ip = i0 + tid;
        float xv = (ip < n) ? x[2 * ip + 1] : 0.5f;
        xs[tid] = fminf(fmaxf(xv, EPSF), 1.0f - EPSF);
    }
    __syncthreads();

    const int tx = tid & 15;        // output col group (8 cols)
    const int ty = tid >> 4;        // output row group (8 rows)

    float acc[8][8];
#pragma unroll
    for (int m = 0; m < 8; m++)
#pragma unroll
        for (int nn = 0; nn < 8; nn++) acc[m][nn] = 0.f;

    for (int k0 = 0; k0 < HDIM; k0 += 16) {
#pragma unroll
        for (int s = 0; s < 8; s++) {
            int idx = tid + s * 256;      // 0..2047
            int kk = idx >> 7;
            int ii = idx & 127;
            As[kk][ii] = fmaxf(fmaf(xs[ii], us[k0 + kk], cs[k0 + kk]), 0.f);
            Bs[kk][ii] = w2[(k0 + kk) * HDIM + j0 + ii];
        }
        __syncthreads();
#pragma unroll
        for (int kk = 0; kk < 16; kk++) {
            float4 a0 = *reinterpret_cast<const float4*>(&As[kk][ty * 8]);
            float4 a1 = *reinterpret_cast<const float4*>(&As[kk][ty * 8 + 4]);
            float4 b0v = *reinterpret_cast<const float4*>(&Bs[kk][tx * 8]);
            float4 b1v = *reinterpret_cast<const float4*>(&Bs[kk][tx * 8 + 4]);
            float a[8] = {a0.x, a0.y, a0.z, a0.w, a1.x, a1.y, a1.z, a1.w};
            float b[8] = {b0v.x, b0v.y, b0v.z, b0v.w, b1v.x, b1v.y, b1v.z, b1v.w};
#pragma unroll
            for (int m = 0; m < 8; m++)
#pragma unroll
                for (int nn = 0; nn < 8; nn++)
                    acc[m][nn] = fmaf(a[m], b[nn], acc[m][nn]);
        }
        __syncthreads();
    }

    float bb[8];
#pragma unroll
    for (int nn = 0; nn < 8; nn++) bb[nn] = b2[j0 + tx * 8 + nn];
#pragma unroll
    for (int m = 0; m < 8; m++) {
        int row = i0 + ty * 8 + m;
        if (row < n) {
#pragma unroll
            for (int nn = 0; nn < 8; nn++)
                g_H2[row * HDIM + j0 + tx * 8 + nn] = fmaxf(acc[m][nn] + bb[nn], 0.f);
        }
    }
}

// ============================================================================
// k2: A = H2 @ M + m0  -> g_A [N][64].  128x64 tile, BK=16, 8x4 microtile.
//     NOTE: A-tile row stride padded to 132 floats (528 B, 16B-aligned) so the
//     float4 LDS reads are aligned (129-float pad caused misaligned address).
// ============================================================================
__global__ void __launch_bounds__(256) k2_amat(int n)
{
    __shared__ float As[16][132];   // H2^T tile, 16B-aligned padded stride
    __shared__ float Bs[16][64];

    const int i0 = blockIdx.x * 128;
    const int tid = threadIdx.x;
    const int tx = tid & 15;        // 16 groups * 4 cols = 64
    const int ty = tid >> 4;        // 16 groups * 8 rows = 128

    float acc[8][4];
#pragma unroll
    for (int m = 0; m < 8; m++)
#pragma unroll
        for (int j = 0; j < 4; j++) acc[m][j] = 0.f;

    for (int k0 = 0; k0 < HDIM; k0 += 16) {
#pragma unroll
        for (int s = 0; s < 2; s++) {
            int e = tid * 2 + s;          // 0..511 float4 units, 4 per row
            int ii = e >> 2;
            int k4 = e & 3;
            float4 v = *reinterpret_cast<const float4*>(&g_H2[(i0 + ii) * HDIM + k0 + k4 * 4]);
            As[k4 * 4 + 0][ii] = v.x;
            As[k4 * 4 + 1][ii] = v.y;
            As[k4 * 4 + 2][ii] = v.z;
            As[k4 * 4 + 3][ii] = v.w;
        }
#pragma unroll
        for (int s = 0; s < 4; s++) {
            int e = tid + s * 256;        // 0..1023
            int kk = e >> 6, jj = e & 63;
            Bs[kk][jj] = g_M[(k0 + kk) * 64 + jj];
        }
        __syncthreads();
#pragma unroll
        for (int kk = 0; kk < 16; kk++) {
            float4 a0 = *reinterpret_cast<const float4*>(&As[kk][ty * 8]);
            float4 a1 = *reinterpret_cast<const float4*>(&As[kk][ty * 8 + 4]);
            float4 bv = *reinterpret_cast<const float4*>(&Bs[kk][tx * 4]);
            float a[8] = {a0.x, a0.y, a0.z, a0.w, a1.x, a1.y, a1.z, a1.w};
            float b[4] = {bv.x, bv.y, bv.z, bv.w};
#pragma unroll
            for (int m = 0; m < 8; m++)
#pragma unroll
                for (int j = 0; j < 4; j++)
                    acc[m][j] = fmaf(a[m], b[j], acc[m][j]);
        }
        __syncthreads();
    }

#pragma unroll
    for (int m = 0; m < 8; m++) {
        int row = i0 + ty * 8 + m;
        if (row < n) {
#pragma unroll
            for (int j = 0; j < 4; j++)
                g_A[row * 64 + tx * 4 + j] = acc[m][j] + g_m0[tx * 4 + j];
        }
    }
}

// ============================================================================
// k3: CPAB closed-form integration, 1 thread per point, A rows in shared.
//     Runs all NC+2=34 iterations (incl. the rounding-drift "no-op" iters)
//     to match the reference's fori_loop semantics.
// ============================================================================
__global__ void __launch_bounds__(128) k3_integrate(const float* __restrict__ x,
                                                    float* __restrict__ out, int n)
{
    __shared__ float sA[128 * 66];  // 64 + 2 pad per row to spread LDS banks
    const int i0 = blockIdx.x * 128;
    const int tid = threadIdx.x;

    for (int e = tid; e < 128 * 64; e += 128) {
        int p = e >> 6, j = e & 63;
        sA[p * 66 + j] = g_A[(i0 + p) * 64 + j];
    }
    __syncthreads();

    int ip = i0 + tid;
    if (ip >= n) return;

    float x2 = x[2 * ip];
    float x1 = x[2 * ip + 1];
    x1 = fminf(fmaxf(x1, EPSF), 1.0f - EPSF);

    float xc = fminf(fmaxf(x2, EPSF), 1.0f - EPSF);
    float t = 1.0f;
    float S = 0.0f;                 // sum a*dt  == log(prod exp(a*dt))
    const float* Ar = &sA[tid * 66];
    const float inv = 1.0f / (float)NCELL;
    const float INF = __int_as_float(0x7f800000);

#pragma unroll 1
    for (int it = 0; it < NCELL + 2; it++) {
        int c = (int)floorf(xc * (float)NCELL);
        c = max(0, min(c, NCELL - 1));
        float a = Ar[2 * c];
        float b = Ar[2 * c + 1];
        float v = a * xc + b;
        float xbnd = ((v >= 0.f) ? (float)(c + 1) : (float)c) * inv;
        bool  small_a = fabsf(a) < TINYF;
        float safe_a = small_a ? 1.0f : a;
        float e = b / safe_a;
        float denom = xc + e;
        float safe_denom = (fabsf(denom) < TINYF) ? ((denom >= 0.f) ? TINYF : -TINYF) : denom;
        float ratio = (xbnd + e) / safe_denom;
        float thit_exp = logf(fmaxf(ratio, TINYF)) / safe_a;
        float safe_b = (fabsf(b) < TINYF) ? TINYF : b;
        float thit_lin = (xbnd - xc) / safe_b;
        float thit = small_a ? thit_lin : ((ratio > TINYF) ? thit_exp : INF);
        thit = (thit <= 0.f) ? INF : thit;
        float dt = fminf(thit, t);
        bool cross = (thit <= t);
        float x_exp = (xc + e) * expf(a * dt) - e;
        float x_lin = xc + b * dt;
        float xn = small_a ? x_lin : x_exp;
        float nudge = (v >= 0.f) ? 1e-7f : -1e-7f;
        xn = cross ? (xbnd + nudge) : xn;
        xn = fminf(fmaxf(xn, EPSF), 1.0f - EPSF);
        S += a * dt;
        t = t - dt;
        xc = xn;
    }

    // outputs: z [N,2] then log_dz_dx [N,2]
    out[2 * ip]     = xc;
    out[2 * ip + 1] = x1;
    out[2 * n + 2 * ip]     = S;
    out[2 * n + 2 * ip + 1] = 0.0f;
}

// ============================================================================
extern "C" void kernel_launch(void* const* d_in, const int* in_sizes, int n_in,
                              void* d_out, int out_size)
{
    const float* x  = (const float*)d_in[0];
    const float* w0 = (const float*)d_in[1];
    const float* b0 = (const float*)d_in[2];
    const float* w1 = (const float*)d_in[3];
    const float* b1 = (const float*)d_in[4];
    const float* w2 = (const float*)d_in[5];
    const float* b2 = (const float*)d_in[6];
    const float* w3 = (const float*)d_in[7];
    const float* b3 = (const float*)d_in[8];
    float* out = (float*)d_out;

    int n = in_sizes[0] / 2;
    if (n > NPTS) n = NPTS;

    k0_prep<<<1, 256>>>(w0, b0, w1, b1, w3, b3);

    dim3 g1((n + 127) / 128, 2);
    k1_mlp<<<g1, 256>>>(x, w2, b2, n);

    k2_amat<<<(n + 127) / 128, 256>>>(n);

    k3_integrate<<<(n + 127) / 128, 128>>>(x, out, n);
}

// round 4
// speedup vs baseline: 4.0569x; 4.0569x over previous
#include <cuda_runtime.h>
#include <math.h>

#define HDIM   256
#define NCELL  32
#define DTH    31
#define EPSF   1e-7f
#define TINYF  1e-10f
#define GTAB   32768                 // table cells; nodes = GTAB+1

// ---------------- device scratch (no cudaMalloc allowed) ----------------
__device__ float g_u[HDIM];
__device__ float g_c[HDIM];
__device__ float g_M[HDIM * 64];            // w3 @ B^T   [256][64]
__device__ float g_m0[64];                  // b3 @ B^T
__device__ float g_H2[(GTAB + 256) * HDIM]; // h2 table (+pad rows for unguarded tile loads)
__device__ float g_Atab[(GTAB + 2) * 64];   // A table rows

// ============================================================================
// k0: reproduce numpy's SVD null-space basis B = Vt[33:].T via Householder LQ
//     (dgesdd Path 4t: dgelqf + dorglq), then fold constants:
//     u,c (layers 0+1 collapse), M = w3@B^T, m0 = b3@B^T.
// ============================================================================
__global__ void k0_prep(const float* __restrict__ w0, const float* __restrict__ b0,
                        const float* __restrict__ w1, const float* __restrict__ b1,
                        const float* __restrict__ w3, const float* __restrict__ b3)
{
    __shared__ double sL[33][64];
    __shared__ double sB[31][64];
    __shared__ double sTau[33];
    const int tid = threadIdx.x;

    for (int idx = tid; idx < 33 * 64; idx += blockDim.x)
        ((double*)sL)[idx] = 0.0;
    __syncthreads();
    if (tid == 0) {
        for (int i = 1; i < NCELL; i++) {
            double xi = (double)i / (double)NCELL;
            sL[i - 1][2 * (i - 1)]     = xi;
            sL[i - 1][2 * (i - 1) + 1] = 1.0;
            sL[i - 1][2 * i]           = -xi;
            sL[i - 1][2 * i + 1]       = -1.0;
        }
        sL[NCELL - 1][1]               = 1.0;
        sL[NCELL][2 * (NCELL - 1)]     = 1.0;
        sL[NCELL][2 * (NCELL - 1) + 1] = 1.0;
    }
    __syncthreads();

    // Householder LQ
    for (int i = 0; i < 33; i++) {
        if (tid == 0) {
            double alpha = sL[i][i];
            double xn2 = 0.0;
            for (int j = i + 1; j < 64; j++) xn2 += sL[i][j] * sL[i][j];
            if (xn2 == 0.0) {
                sTau[i] = 0.0;
            } else {
                double beta = sqrt(alpha * alpha + xn2);
                beta = (alpha >= 0.0) ? -beta : beta;
                sTau[i] = (beta - alpha) / beta;
                double sc = 1.0 / (alpha - beta);
                for (int j = i + 1; j < 64; j++) sL[i][j] *= sc;
                sL[i][i] = beta;
            }
        }
        __syncthreads();
        double tau = sTau[i];
        if (tau != 0.0) {
            int r = i + 1 + tid;
            if (r < 33) {
                double w = sL[r][i];
                for (int j = i + 1; j < 64; j++) w += sL[r][j] * sL[i][j];
                w *= tau;
                sL[r][i] -= w;
                for (int j = i + 1; j < 64; j++) sL[r][j] -= w * sL[i][j];
            }
        }
        __syncthreads();
    }

    // Rows 33..63 of Q
    for (int idx = tid; idx < 31 * 64; idx += blockDim.x)
        ((double*)sB)[idx] = 0.0;
    __syncthreads();
    if (tid < 31) sB[tid][33 + tid] = 1.0;
    __syncthreads();
    for (int i = 32; i >= 0; i--) {
        double tau = sTau[i];
        if (tau != 0.0 && tid < 31) {
            int r = tid;
            double w = sB[r][i];
            for (int j = i + 1; j < 64; j++) w += sB[r][j] * sL[i][j];
            w *= tau;
            sB[r][i] -= w;
            for (int j = i + 1; j < 64; j++) sB[r][j] -= w * sL[i][j];
        }
        __syncthreads();
    }
    // sB[d][j64] == B[j64][d]

    if (tid < HDIM) {
        float uu = 0.f, cc = 0.f;
        for (int k = 0; k < HDIM; k++) {
            float wv = w1[k * HDIM + tid];
            uu = fmaf(w0[k], wv, uu);
            cc = fmaf(b0[k], wv, cc);
        }
        g_u[tid] = uu;
        g_c[tid] = cc + b1[tid];
    }
    for (int idx = tid; idx < HDIM * 64; idx += blockDim.x) {
        int k = idx >> 6, j = idx & 63;
        float s = 0.f;
        for (int d = 0; d < DTH; d++)
            s = fmaf(w3[k * DTH + d], (float)sB[d][j], s);
        g_M[idx] = s;
    }
    if (tid < 64) {
        float s = 0.f;
        for (int d = 0; d < DTH; d++)
            s = fmaf(b3[d], (float)sB[d][tid], s);
        g_m0[tid] = s;
    }
}

// ============================================================================
// kT1: h2 table.  H2[g] = relu( relu(x_g*u + c) @ w2 + b2 ), x_g = g/GTAB.
//      128x128 tile, BK=16, 8x8 microtile.  nrows = GTAB+1.
// ============================================================================
__global__ void __launch_bounds__(256) kT1_h2tab(const float* __restrict__ w2,
                                                 const float* __restrict__ b2, int nrows)
{
    __shared__ float As[16][128];
    __shared__ float Bs[16][128];
    __shared__ float xs[128];
    __shared__ float us[HDIM], cs[HDIM];

    const int i0 = blockIdx.x * 128;
    const int j0 = blockIdx.y * 128;
    const int tid = threadIdx.x;

    us[tid] = g_u[tid];
    cs[tid] = g_c[tid];
    if (tid < 128)
        xs[tid] = (float)(i0 + tid) * (1.0f / (float)GTAB);
    __syncthreads();

    const int tx = tid & 15;
    const int ty = tid >> 4;

    float acc[8][8];
#pragma unroll
    for (int m = 0; m < 8; m++)
#pragma unroll
        for (int nn = 0; nn < 8; nn++) acc[m][nn] = 0.f;

    for (int k0 = 0; k0 < HDIM; k0 += 16) {
#pragma unroll
        for (int s = 0; s < 8; s++) {
            int idx = tid + s * 256;
            int kk = idx >> 7;
            int ii = idx & 127;
            As[kk][ii] = fmaxf(fmaf(xs[ii], us[k0 + kk], cs[k0 + kk]), 0.f);
            Bs[kk][ii] = w2[(k0 + kk) * HDIM + j0 + ii];
        }
        __syncthreads();
#pragma unroll
        for (int kk = 0; kk < 16; kk++) {
            float4 a0 = *reinterpret_cast<const float4*>(&As[kk][ty * 8]);
            float4 a1 = *reinterpret_cast<const float4*>(&As[kk][ty * 8 + 4]);
            float4 b0v = *reinterpret_cast<const float4*>(&Bs[kk][tx * 8]);
            float4 b1v = *reinterpret_cast<const float4*>(&Bs[kk][tx * 8 + 4]);
            float a[8] = {a0.x, a0.y, a0.z, a0.w, a1.x, a1.y, a1.z, a1.w};
            float b[8] = {b0v.x, b0v.y, b0v.z, b0v.w, b1v.x, b1v.y, b1v.z, b1v.w};
#pragma unroll
            for (int m = 0; m < 8; m++)
#pragma unroll
                for (int nn = 0; nn < 8; nn++)
                    acc[m][nn] = fmaf(a[m], b[nn], acc[m][nn]);
        }
        __syncthreads();
    }

    float bb[8];
#pragma unroll
    for (int nn = 0; nn < 8; nn++) bb[nn] = b2[j0 + tx * 8 + nn];
#pragma unroll
    for (int m = 0; m < 8; m++) {
        int row = i0 + ty * 8 + m;
        if (row < nrows) {
#pragma unroll
            for (int nn = 0; nn < 8; nn++)
                g_H2[row * HDIM + j0 + tx * 8 + nn] = fmaxf(acc[m][nn] + bb[nn], 0.f);
        }
    }
}

// ============================================================================
// kT2: A table.  Atab = H2tab @ M + m0.  128x64 tile, BK=16, 8x4 microtile.
//      A-tile row stride 132 floats (16B-aligned).
// ============================================================================
__global__ void __launch_bounds__(256) kT2_atab(int nrows)
{
    __shared__ float As[16][132];
    __shared__ float Bs[16][64];

    const int i0 = blockIdx.x * 128;
    const int tid = threadIdx.x;
    const int tx = tid & 15;
    const int ty = tid >> 4;

    float acc[8][4];
#pragma unroll
    for (int m = 0; m < 8; m++)
#pragma unroll
        for (int j = 0; j < 4; j++) acc[m][j] = 0.f;

    for (int k0 = 0; k0 < HDIM; k0 += 16) {
#pragma unroll
        for (int s = 0; s < 2; s++) {
            int e = tid * 2 + s;
            int ii = e >> 2;
            int k4 = e & 3;
            float4 v = *reinterpret_cast<const float4*>(&g_H2[(i0 + ii) * HDIM + k0 + k4 * 4]);
            As[k4 * 4 + 0][ii] = v.x;
            As[k4 * 4 + 1][ii] = v.y;
            As[k4 * 4 + 2][ii] = v.z;
            As[k4 * 4 + 3][ii] = v.w;
        }
#pragma unroll
        for (int s = 0; s < 4; s++) {
            int e = tid + s * 256;
            int kk = e >> 6, jj = e & 63;
            Bs[kk][jj] = g_M[(k0 + kk) * 64 + jj];
        }
        __syncthreads();
#pragma unroll
        for (int kk = 0; kk < 16; kk++) {
            float4 a0 = *reinterpret_cast<const float4*>(&As[kk][ty * 8]);
            float4 a1 = *reinterpret_cast<const float4*>(&As[kk][ty * 8 + 4]);
            float4 bv = *reinterpret_cast<const float4*>(&Bs[kk][tx * 4]);
            float a[8] = {a0.x, a0.y, a0.z, a0.w, a1.x, a1.y, a1.z, a1.w};
            float b[4] = {bv.x, bv.y, bv.z, bv.w};
#pragma unroll
            for (int m = 0; m < 8; m++)
#pragma unroll
                for (int j = 0; j < 4; j++)
                    acc[m][j] = fmaf(a[m], b[j], acc[m][j]);
        }
        __syncthreads();
    }

#pragma unroll
    for (int m = 0; m < 8; m++) {
        int row = i0 + ty * 8 + m;
        if (row < nrows) {
#pragma unroll
            for (int j = 0; j < 4; j++)
                g_Atab[row * 64 + tx * 4 + j] = acc[m][j] + g_m0[tx * 4 + j];
        }
    }
}

// ============================================================================
// k3: per-point lerp of the A row from the table + CPAB closed-form
//     integration (all NC+2=34 iterations to match the reference fori_loop).
// ============================================================================
__global__ void __launch_bounds__(128) k3_integrate(const float* __restrict__ x,
                                                    float* __restrict__ out, int n)
{
    __shared__ float sA[128 * 66];
    __shared__ int   sIdx[128];
    __shared__ float sFrac[128];

    const int i0 = blockIdx.x * 128;
    const int tid = threadIdx.x;
    const int ip = i0 + tid;

    // per-point table index + fraction
    float x1 = (ip < n) ? x[2 * ip + 1] : 0.5f;
    x1 = fminf(fmaxf(x1, EPSF), 1.0f - EPSF);
    {
        float f = x1 * (float)GTAB;
        int i = (int)floorf(f);
        i = max(0, min(i, GTAB - 1));
        sIdx[tid] = i;
        sFrac[tid] = f - (float)i;
    }
    __syncthreads();

    // cooperative coalesced lerp: 64 consecutive threads fetch one 64-float row
    for (int e = tid; e < 128 * 64; e += 128) {
        int p = e >> 6, j = e & 63;
        int r = sIdx[p];
        float fr = sFrac[p];
        float v0 = g_Atab[r * 64 + j];
        float v1 = g_Atab[(r + 1) * 64 + j];
        sA[p * 66 + j] = fmaf(fr, v1 - v0, v0);
    }
    __syncthreads();

    if (ip >= n) return;

    float x2 = x[2 * ip];
    float xc = fminf(fmaxf(x2, EPSF), 1.0f - EPSF);
    float t = 1.0f;
    float S = 0.0f;                 // sum a*dt == log(prod exp(a*dt))
    const float* Ar = &sA[tid * 66];
    const float inv = 1.0f / (float)NCELL;
    const float INF = __int_as_float(0x7f800000);

#pragma unroll 1
    for (int it = 0; it < NCELL + 2; it++) {
        int c = (int)floorf(xc * (float)NCELL);
        c = max(0, min(c, NCELL - 1));
        float a = Ar[2 * c];
        float b = Ar[2 * c + 1];
        float v = a * xc + b;
        float xbnd = ((v >= 0.f) ? (float)(c + 1) : (float)c) * inv;
        bool  small_a = fabsf(a) < TINYF;
        float safe_a = small_a ? 1.0f : a;
        float e = b / safe_a;
        float denom = xc + e;
        float safe_denom = (fabsf(denom) < TINYF) ? ((denom >= 0.f) ? TINYF : -TINYF) : denom;
        float ratio = (xbnd + e) / safe_denom;
        float thit_exp = logf(fmaxf(ratio, TINYF)) / safe_a;
        float safe_b = (fabsf(b) < TINYF) ? TINYF : b;
        float thit_lin = (xbnd - xc) / safe_b;
        float thit = small_a ? thit_lin : ((ratio > TINYF) ? thit_exp : INF);
        thit = (thit <= 0.f) ? INF : thit;
        float dt = fminf(thit, t);
        bool cross = (thit <= t);
        float x_exp = (xc + e) * expf(a * dt) - e;
        float x_lin = xc + b * dt;
        float xn = small_a ? x_lin : x_exp;
        float nudge = (v >= 0.f) ? 1e-7f : -1e-7f;
        xn = cross ? (xbnd + nudge) : xn;
        xn = fminf(fmaxf(xn, EPSF), 1.0f - EPSF);
        S += a * dt;
        t = t - dt;
        xc = xn;
    }

    // outputs: z [N,2] then log_dz_dx [N,2]
    out[2 * ip]     = xc;
    out[2 * ip + 1] = x1;
    out[2 * n + 2 * ip]     = S;
    out[2 * n + 2 * ip + 1] = 0.0f;
}

// ============================================================================
extern "C" void kernel_launch(void* const* d_in, const int* in_sizes, int n_in,
                              void* d_out, int out_size)
{
    const float* x  = (const float*)d_in[0];
    const float* w0 = (const float*)d_in[1];
    const float* b0 = (const float*)d_in[2];
    const float* w1 = (const float*)d_in[3];
    const float* b1 = (const float*)d_in[4];
    const float* w2 = (const float*)d_in[5];
    const float* b2 = (const float*)d_in[6];
    const float* w3 = (const float*)d_in[7];
    const float* b3 = (const float*)d_in[8];
    float* out = (float*)d_out;

    int n = in_sizes[0] / 2;
    const int nrows = GTAB + 1;

    k0_prep<<<1, 256>>>(w0, b0, w1, b1, w3, b3);

    dim3 g1((nrows + 127) / 128, 2);
    kT1_h2tab<<<g1, 256>>>(w2, b2, nrows);

    kT2_atab<<<(nrows + 127) / 128, 256>>>(nrows);

    k3_integrate<<<(n + 127) / 128, 128>>>(x, out, n);
}

// round 5
// speedup vs baseline: 9.8583x; 2.4300x over previous
#include <cuda_runtime.h>
#include <math.h>

#define HDIM   256
#define NCELL  32
#define DTH    31
#define EPSF   1e-7f
#define TINYF  1e-10f
#define GTAB   8192                  // table cells; nodes = GTAB+1

// ---------------- device scratch (no cudaMalloc allowed) ----------------
__device__ float g_u[HDIM];
__device__ float g_c[HDIM];
__device__ float g_M[HDIM * 64];            // w3 @ B^T   [256][64]
__device__ float g_m0[64];                  // b3 @ B^T
__device__ float g_H2[(GTAB + 256) * HDIM]; // h2 table (+pad rows for unguarded tile loads)
__device__ float g_Atab[(GTAB + 2) * 64];   // A table rows

__device__ __forceinline__ double warpReduceAddD(double v) {
#pragma unroll
    for (int o = 16; o > 0; o >>= 1)
        v += __shfl_down_sync(0xffffffffu, v, o);
    return v;
}

// ============================================================================
// k0: numpy SVD null-space basis B = Vt[33:].T via Householder LQ
//     (dgesdd Path 4t: dgelqf + dorglq), PARALLELIZED (warp reductions,
//     warp-per-row reflector application; fp64 chains were the bottleneck).
//     Then fold constants: u,c (layers 0+1 collapse), M = w3@B^T, m0 = b3@B^T.
// ============================================================================
__global__ void k0_prep(const float* __restrict__ w0, const float* __restrict__ b0,
                        const float* __restrict__ w1, const float* __restrict__ b1,
                        const float* __restrict__ w3, const float* __restrict__ b3)
{
    __shared__ double sL[33][64];
    __shared__ double sB[31][64];
    __shared__ double sTau[33];
    __shared__ double sSc;
    const int tid  = threadIdx.x;
    const int lane = tid & 31;
    const int wrp  = tid >> 5;          // 8 warps @ 256 threads

    for (int idx = tid; idx < 33 * 64; idx += blockDim.x)
        ((double*)sL)[idx] = 0.0;
    __syncthreads();
    if (tid == 0) {
        for (int i = 1; i < NCELL; i++) {
            double xi = (double)i / (double)NCELL;
            sL[i - 1][2 * (i - 1)]     = xi;
            sL[i - 1][2 * (i - 1) + 1] = 1.0;
            sL[i - 1][2 * i]           = -xi;
            sL[i - 1][2 * i + 1]       = -1.0;
        }
        sL[NCELL - 1][1]               = 1.0;
        sL[NCELL][2 * (NCELL - 1)]     = 1.0;
        sL[NCELL][2 * (NCELL - 1) + 1] = 1.0;
    }
    __syncthreads();

    // ---- dgelqf: 33 Householder reflectors over columns i..63 ----
    for (int i = 0; i < 33; i++) {
        if (wrp == 0) {
            double p = 0.0;
            for (int j = i + 1 + lane; j < 64; j += 32) p += sL[i][j] * sL[i][j];
            p = warpReduceAddD(p);
            if (lane == 0) {
                double alpha = sL[i][i];
                if (p == 0.0) {
                    sTau[i] = 0.0;
                } else {
                    double beta = sqrt(alpha * alpha + p);
                    beta = (alpha >= 0.0) ? -beta : beta;
                    sTau[i] = (beta - alpha) / beta;
                    sSc = 1.0 / (alpha - beta);
                    sL[i][i] = beta;
                }
            }
        }
        __syncthreads();
        double tau = sTau[i];
        if (tau != 0.0) {
            // scale tail of row i
            if (tid < 64) {
                int j = i + 1 + tid;
                if (j < 64) sL[i][j] *= sSc;
            }
        }
        __syncthreads();
        if (tau != 0.0) {
            // apply reflector to rows i+1..32 (warp-per-row)
            for (int r = i + 1 + wrp; r < 33; r += 8) {
                double p = (lane == 0) ? sL[r][i] : 0.0;
                for (int j = i + 1 + lane; j < 64; j += 32) p += sL[r][j] * sL[i][j];
                p = warpReduceAddD(p);
                p = __shfl_sync(0xffffffffu, p, 0) * tau;
                if (lane == 0) sL[r][i] -= p;
                for (int j = i + 1 + lane; j < 64; j += 32) sL[r][j] -= p * sL[i][j];
            }
        }
        __syncthreads();
    }

    // ---- dorglq rows 33..63: E = [0 | I_31], apply H(32)..H(0) on the right ----
    for (int idx = tid; idx < 31 * 64; idx += blockDim.x)
        ((double*)sB)[idx] = 0.0;
    __syncthreads();
    if (tid < 31) sB[tid][33 + tid] = 1.0;
    __syncthreads();
    for (int i = 32; i >= 0; i--) {
        double tau = sTau[i];
        if (tau != 0.0) {
            for (int r = wrp; r < 31; r += 8) {
                double p = (lane == 0) ? sB[r][i] : 0.0;
                for (int j = i + 1 + lane; j < 64; j += 32) p += sB[r][j] * sL[i][j];
                p = warpReduceAddD(p);
                p = __shfl_sync(0xffffffffu, p, 0) * tau;
                if (lane == 0) sB[r][i] -= p;
                for (int j = i + 1 + lane; j < 64; j += 32) sB[r][j] -= p * sL[i][j];
            }
        }
        __syncthreads();
    }
    // sB[d][j64] == B[j64][d]

    if (tid < HDIM) {
        float uu = 0.f, cc = 0.f;
        for (int k = 0; k < HDIM; k++) {
            float wv = w1[k * HDIM + tid];
            uu = fmaf(w0[k], wv, uu);
            cc = fmaf(b0[k], wv, cc);
        }
        g_u[tid] = uu;
        g_c[tid] = cc + b1[tid];
    }
    for (int idx = tid; idx < HDIM * 64; idx += blockDim.x) {
        int k = idx >> 6, j = idx & 63;
        float s = 0.f;
        for (int d = 0; d < DTH; d++)
            s = fmaf(w3[k * DTH + d], (float)sB[d][j], s);
        g_M[idx] = s;
    }
    if (tid < 64) {
        float s = 0.f;
        for (int d = 0; d < DTH; d++)
            s = fmaf(b3[d], (float)sB[d][tid], s);
        g_m0[tid] = s;
    }
}

// ============================================================================
// kT1: h2 table.  H2[g] = relu( relu(x_g*u + c) @ w2 + b2 ), x_g = g/GTAB.
// ============================================================================
__global__ void __launch_bounds__(256) kT1_h2tab(const float* __restrict__ w2,
                                                 const float* __restrict__ b2, int nrows)
{
    __shared__ float As[16][128];
    __shared__ float Bs[16][128];
    __shared__ float xs[128];
    __shared__ float us[HDIM], cs[HDIM];

    const int i0 = blockIdx.x * 128;
    const int j0 = blockIdx.y * 128;
    const int tid = threadIdx.x;

    us[tid] = g_u[tid];
    cs[tid] = g_c[tid];
    if (tid < 128)
        xs[tid] = (float)(i0 + tid) * (1.0f / (float)GTAB);
    __syncthreads();

    const int tx = tid & 15;
    const int ty = tid >> 4;

    float acc[8][8];
#pragma unroll
    for (int m = 0; m < 8; m++)
#pragma unroll
        for (int nn = 0; nn < 8; nn++) acc[m][nn] = 0.f;

    for (int k0 = 0; k0 < HDIM; k0 += 16) {
#pragma unroll
        for (int s = 0; s < 8; s++) {
            int idx = tid + s * 256;
            int kk = idx >> 7;
            int ii = idx & 127;
            As[kk][ii] = fmaxf(fmaf(xs[ii], us[k0 + kk], cs[k0 + kk]), 0.f);
            Bs[kk][ii] = w2[(k0 + kk) * HDIM + j0 + ii];
        }
        __syncthreads();
#pragma unroll
        for (int kk = 0; kk < 16; kk++) {
            float4 a0 = *reinterpret_cast<const float4*>(&As[kk][ty * 8]);
            float4 a1 = *reinterpret_cast<const float4*>(&As[kk][ty * 8 + 4]);
            float4 b0v = *reinterpret_cast<const float4*>(&Bs[kk][tx * 8]);
            float4 b1v = *reinterpret_cast<const float4*>(&Bs[kk][tx * 8 + 4]);
            float a[8] = {a0.x, a0.y, a0.z, a0.w, a1.x, a1.y, a1.z, a1.w};
            float b[8] = {b0v.x, b0v.y, b0v.z, b0v.w, b1v.x, b1v.y, b1v.z, b1v.w};
#pragma unroll
            for (int m = 0; m < 8; m++)
#pragma unroll
                for (int nn = 0; nn < 8; nn++)
                    acc[m][nn] = fmaf(a[m], b[nn], acc[m][nn]);
        }
        __syncthreads();
    }

    float bb[8];
#pragma unroll
    for (int nn = 0; nn < 8; nn++) bb[nn] = b2[j0 + tx * 8 + nn];
#pragma unroll
    for (int m = 0; m < 8; m++) {
        int row = i0 + ty * 8 + m;
        if (row < nrows) {
#pragma unroll
            for (int nn = 0; nn < 8; nn++)
                g_H2[row * HDIM + j0 + tx * 8 + nn] = fmaxf(acc[m][nn] + bb[nn], 0.f);
        }
    }
}

// ============================================================================
// kT2: A table.  Atab = H2tab @ M + m0.
// ============================================================================
__global__ void __launch_bounds__(256) kT2_atab(int nrows)
{
    __shared__ float As[16][132];
    __shared__ float Bs[16][64];

    const int i0 = blockIdx.x * 128;
    const int tid = threadIdx.x;
    const int tx = tid & 15;
    const int ty = tid >> 4;

    float acc[8][4];
#pragma unroll
    for (int m = 0; m < 8; m++)
#pragma unroll
        for (int j = 0; j < 4; j++) acc[m][j] = 0.f;

    for (int k0 = 0; k0 < HDIM; k0 += 16) {
#pragma unroll
        for (int s = 0; s < 2; s++) {
            int e = tid * 2 + s;
            int ii = e >> 2;
            int k4 = e & 3;
            float4 v = *reinterpret_cast<const float4*>(&g_H2[(i0 + ii) * HDIM + k0 + k4 * 4]);
            As[k4 * 4 + 0][ii] = v.x;
            As[k4 * 4 + 1][ii] = v.y;
            As[k4 * 4 + 2][ii] = v.z;
            As[k4 * 4 + 3][ii] = v.w;
        }
#pragma unroll
        for (int s = 0; s < 4; s++) {
            int e = tid + s * 256;
            int kk = e >> 6, jj = e & 63;
            Bs[kk][jj] = g_M[(k0 + kk) * 64 + jj];
        }
        __syncthreads();
#pragma unroll
        for (int kk = 0; kk < 16; kk++) {
            float4 a0 = *reinterpret_cast<const float4*>(&As[kk][ty * 8]);
            float4 a1 = *reinterpret_cast<const float4*>(&As[kk][ty * 8 + 4]);
            float4 bv = *reinterpret_cast<const float4*>(&Bs[kk][tx * 4]);
            float a[8] = {a0.x, a0.y, a0.z, a0.w, a1.x, a1.y, a1.z, a1.w};
            float b[4] = {bv.x, bv.y, bv.z, bv.w};
#pragma unroll
            for (int m = 0; m < 8; m++)
#pragma unroll
                for (int j = 0; j < 4; j++)
                    acc[m][j] = fmaf(a[m], b[j], acc[m][j]);
        }
        __syncthreads();
    }

#pragma unroll
    for (int m = 0; m < 8; m++) {
        int row = i0 + ty * 8 + m;
        if (row < nrows) {
#pragma unroll
            for (int j = 0; j < 4; j++)
                g_Atab[row * 64 + tx * 4 + j] = acc[m][j] + g_m0[tx * 4 + j];
        }
    }
}

// ============================================================================
// k3: per-point lerp of A row from table + CPAB closed-form integration.
//     Exact early-exit: once an iteration has dt==0 && xn==xc, all later
//     iterations are bit-identical (fixpoint; __expf(0)==1 exactly), so a
//     warp-wide break preserves exact reference semantics.
//     Fast intrinsics on crossing-time math; precise '/' kept for e=b/a
//     (its exact rounding drives the reference-matching drift iterations).
// ============================================================================
__global__ void __launch_bounds__(128) k3_integrate(const float* __restrict__ x,
                                                    float* __restrict__ out, int n)
{
    __shared__ float sA[128 * 66];
    __shared__ int   sIdx[128];
    __shared__ float sFrac[128];

    const int i0 = blockIdx.x * 128;
    const int tid = threadIdx.x;
    const int ip = i0 + tid;
    const bool valid = (ip < n);

    float x1 = valid ? x[2 * ip + 1] : 0.5f;
    x1 = fminf(fmaxf(x1, EPSF), 1.0f - EPSF);
    {
        float f = x1 * (float)GTAB;
        int i = (int)f;
        i = max(0, min(i, GTAB - 1));
        sIdx[tid] = i;
        sFrac[tid] = f - (float)i;
    }
    __syncthreads();

    // coalesced lerp: 64 consecutive threads fetch one 64-float row pair
    for (int e = tid; e < 128 * 64; e += 128) {
        int p = e >> 6, j = e & 63;
        int r = sIdx[p];
        float fr = sFrac[p];
        float v0 = g_Atab[r * 64 + j];
        float v1 = g_Atab[(r + 1) * 64 + j];
        sA[p * 66 + j] = fmaf(fr, v1 - v0, v0);
    }
    __syncthreads();

    float x2 = valid ? x[2 * ip] : 0.5f;
    float xc = fminf(fmaxf(x2, EPSF), 1.0f - EPSF);
    float t = 1.0f;
    float S = 0.0f;
    const float* Ar = &sA[tid * 66];
    const float inv = 1.0f / (float)NCELL;
    const float INF = __int_as_float(0x7f800000);

#pragma unroll 1
    for (int it = 0; it < NCELL + 2; it++) {
        int c = (int)(xc * (float)NCELL);
        c = max(0, min(c, NCELL - 1));
        float a = Ar[2 * c];
        float b = Ar[2 * c + 1];
        float v = a * xc + b;
        float xbnd = ((v >= 0.f) ? (float)(c + 1) : (float)c) * inv;
        bool  small_a = fabsf(a) < TINYF;
        float safe_a = small_a ? 1.0f : a;
        float e = b / safe_a;                       // precise: drives drift matching
        float denom = xc + e;
        float safe_denom = (fabsf(denom) < TINYF) ? ((denom >= 0.f) ? TINYF : -TINYF) : denom;
        float ratio = __fdividef(xbnd + e, safe_denom);
        float thit_exp = __fdividef(__logf(fmaxf(ratio, TINYF)), safe_a);
        float safe_b = (fabsf(b) < TINYF) ? TINYF : b;
        float thit_lin = __fdividef(xbnd - xc, safe_b);
        float thit = small_a ? thit_lin : ((ratio > TINYF) ? thit_exp : INF);
        thit = (thit <= 0.f) ? INF : thit;
        float dt = fminf(thit, t);
        bool cross = (thit <= t);
        float x_exp = (xc + e) * __expf(a * dt) - e;
        float x_lin = xc + b * dt;
        float xn = small_a ? x_lin : x_exp;
        float nudge = (v >= 0.f) ? 1e-7f : -1e-7f;
        xn = cross ? (xbnd + nudge) : xn;
        xn = fminf(fmaxf(xn, EPSF), 1.0f - EPSF);
        S += a * dt;
        t = t - dt;
        bool done = (dt == 0.0f) && (xn == xc);     // exact fixpoint
        xc = xn;
        if (__all_sync(0xffffffffu, done)) break;
    }

    if (valid) {
        out[2 * ip]     = xc;
        out[2 * ip + 1] = x1;
        out[2 * n + 2 * ip]     = S;
        out[2 * n + 2 * ip + 1] = 0.0f;
    }
}

// ============================================================================
extern "C" void kernel_launch(void* const* d_in, const int* in_sizes, int n_in,
                              void* d_out, int out_size)
{
    const float* x  = (const float*)d_in[0];
    const float* w0 = (const float*)d_in[1];
    const float* b0 = (const float*)d_in[2];
    const float* w1 = (const float*)d_in[3];
    const float* b1 = (const float*)d_in[4];
    const float* w2 = (const float*)d_in[5];
    const float* b2 = (const float*)d_in[6];
    const float* w3 = (const float*)d_in[7];
    const float* b3 = (const float*)d_in[8];
    float* out = (float*)d_out;

    int n = in_sizes[0] / 2;
    const int nrows = GTAB + 1;

    k0_prep<<<1, 256>>>(w0, b0, w1, b1, w3, b3);

    dim3 g1((nrows + 127) / 128, 2);
    kT1_h2tab<<<g1, 256>>>(w2, b2, nrows);

    kT2_atab<<<(nrows + 127) / 128, 256>>>(nrows);

    k3_integrate<<<(n + 127) / 128, 128>>>(x, out, n);
}

// round 6
// speedup vs baseline: 16.7922x; 1.7034x over previous
#include <cuda_runtime.h>
#include <math.h>

#define HDIM   256
#define NCELL  32
#define DTH    31
#define EPSF   1e-7f
#define TINYF  1e-10f
#define GTAB   4096                  // table cells; nodes = GTAB+1

// ---------------- device scratch (no cudaMalloc allowed) ----------------
__device__ float g_u[HDIM];
__device__ float g_c[HDIM];
__device__ float g_M[HDIM * 64];            // w3 @ B^T   [256][64]
__device__ float g_m0[64];                  // b3 @ B^T
__device__ float g_H2[(GTAB + 256) * HDIM]; // h2 table (+pad rows for unguarded tile loads)
__device__ float g_Atab[(GTAB + 2) * 64];   // A table rows

__device__ __forceinline__ double warpReduceAddD(double v) {
#pragma unroll
    for (int o = 16; o > 0; o >>= 1)
        v += __shfl_down_sync(0xffffffffu, v, o);
    return v;
}

// ============================================================================
// k0: numpy SVD null-space basis B = Vt[33:].T via Householder LQ
//     (dgesdd Path 4t: dgelqf + dorglq). 1024 threads: warp-per-row reflector
//     application is now fully parallel across rows (was 4-deep serial).
//     Then fold constants: u,c (layers 0+1 collapse), M = w3@B^T, m0 = b3@B^T.
// ============================================================================
__global__ void __launch_bounds__(1024) k0_prep(
    const float* __restrict__ w0, const float* __restrict__ b0,
    const float* __restrict__ w1, const float* __restrict__ b1,
    const float* __restrict__ w3, const float* __restrict__ b3)
{
    __shared__ double sL[33][64];
    __shared__ double sB[31][64];
    __shared__ double sTau[33];
    __shared__ double sSc;
    const int tid  = threadIdx.x;
    const int lane = tid & 31;
    const int wrp  = tid >> 5;          // 32 warps

    for (int idx = tid; idx < 33 * 64; idx += blockDim.x)
        ((double*)sL)[idx] = 0.0;
    __syncthreads();
    if (tid == 0) {
        for (int i = 1; i < NCELL; i++) {
            double xi = (double)i / (double)NCELL;
            sL[i - 1][2 * (i - 1)]     = xi;
            sL[i - 1][2 * (i - 1) + 1] = 1.0;
            sL[i - 1][2 * i]           = -xi;
            sL[i - 1][2 * i + 1]       = -1.0;
        }
        sL[NCELL - 1][1]               = 1.0;
        sL[NCELL][2 * (NCELL - 1)]     = 1.0;
        sL[NCELL][2 * (NCELL - 1) + 1] = 1.0;
    }
    __syncthreads();

    // ---- dgelqf: 33 Householder reflectors over columns i..63 ----
    for (int i = 0; i < 33; i++) {
        if (wrp == 0) {
            double p = 0.0;
            for (int j = i + 1 + lane; j < 64; j += 32) p += sL[i][j] * sL[i][j];
            p = warpReduceAddD(p);
            if (lane == 0) {
                double alpha = sL[i][i];
                if (p == 0.0) {
                    sTau[i] = 0.0;
                } else {
                    double beta = sqrt(alpha * alpha + p);
                    beta = (alpha >= 0.0) ? -beta : beta;
                    sTau[i] = (beta - alpha) / beta;
                    sSc = 1.0 / (alpha - beta);
                    sL[i][i] = beta;
                }
            }
        }
        __syncthreads();
        double tau = sTau[i];
        if (tau != 0.0) {
            if (tid < 64) {
                int j = i + 1 + tid;
                if (j < 64) sL[i][j] *= sSc;
            }
        }
        __syncthreads();
        if (tau != 0.0) {
            int r = i + 1 + wrp;               // one row per warp, all parallel
            if (r < 33) {
                double p = (lane == 0) ? sL[r][i] : 0.0;
                for (int j = i + 1 + lane; j < 64; j += 32) p += sL[r][j] * sL[i][j];
                p = warpReduceAddD(p);
                p = __shfl_sync(0xffffffffu, p, 0) * tau;
                if (lane == 0) sL[r][i] -= p;
                for (int j = i + 1 + lane; j < 64; j += 32) sL[r][j] -= p * sL[i][j];
            }
        }
        __syncthreads();
    }

    // ---- dorglq rows 33..63: E = [0 | I_31], apply H(32)..H(0) on the right ----
    for (int idx = tid; idx < 31 * 64; idx += blockDim.x)
        ((double*)sB)[idx] = 0.0;
    __syncthreads();
    if (tid < 31) sB[tid][33 + tid] = 1.0;
    __syncthreads();
    for (int i = 32; i >= 0; i--) {
        double tau = sTau[i];
        if (tau != 0.0) {
            int r = wrp;                       // one row per warp, all 31 parallel
            if (r < 31) {
                double p = (lane == 0) ? sB[r][i] : 0.0;
                for (int j = i + 1 + lane; j < 64; j += 32) p += sB[r][j] * sL[i][j];
                p = warpReduceAddD(p);
                p = __shfl_sync(0xffffffffu, p, 0) * tau;
                if (lane == 0) sB[r][i] -= p;
                for (int j = i + 1 + lane; j < 64; j += 32) sB[r][j] -= p * sL[i][j];
            }
        }
        __syncthreads();
    }
    // sB[d][j64] == B[j64][d]

    if (tid < HDIM) {
        float uu = 0.f, cc = 0.f;
        for (int k = 0; k < HDIM; k++) {
            float wv = w1[k * HDIM + tid];
            uu = fmaf(w0[k], wv, uu);
            cc = fmaf(b0[k], wv, cc);
        }
        g_u[tid] = uu;
        g_c[tid] = cc + b1[tid];
    }
    for (int idx = tid; idx < HDIM * 64; idx += blockDim.x) {
        int k = idx >> 6, j = idx & 63;
        float s = 0.f;
        for (int d = 0; d < DTH; d++)
            s = fmaf(w3[k * DTH + d], (float)sB[d][j], s);
        g_M[idx] = s;
    }
    if (tid < 64) {
        float s = 0.f;
        for (int d = 0; d < DTH; d++)
            s = fmaf(b3[d], (float)sB[d][tid], s);
        g_m0[tid] = s;
    }
}

// ============================================================================
// kT1: h2 table.  H2[g] = relu( relu(x_g*u + c) @ w2 + b2 ), x_g = g/GTAB.
//      64x128 tile (more blocks -> fills 148 SMs at small row counts),
//      BK=16, 8x8 microtile, 128 threads.
// ============================================================================
__global__ void __launch_bounds__(128) kT1_h2tab(const float* __restrict__ w2,
                                                 const float* __restrict__ b2, int nrows)
{
    __shared__ float As[16][64];
    __shared__ float Bs[16][128];
    __shared__ float xs[64];
    __shared__ float us[HDIM], cs[HDIM];

    const int i0 = blockIdx.x * 64;
    const int j0 = blockIdx.y * 128;
    const int tid = threadIdx.x;

    us[tid] = g_u[tid];        us[tid + 128] = g_u[tid + 128];
    cs[tid] = g_c[tid];        cs[tid + 128] = g_c[tid + 128];
    if (tid < 64)
        xs[tid] = (float)(i0 + tid) * (1.0f / (float)GTAB);
    __syncthreads();

    const int tx = tid & 15;          // 16 col groups of 8
    const int ty = tid >> 4;          // 8 row groups of 8

    float acc[8][8];
#pragma unroll
    for (int m = 0; m < 8; m++)
#pragma unroll
        for (int nn = 0; nn < 8; nn++) acc[m][nn] = 0.f;

    for (int k0 = 0; k0 < HDIM; k0 += 16) {
#pragma unroll
        for (int s = 0; s < 8; s++) {           // As: 1024 elems
            int idx = tid + s * 128;
            int kk = idx >> 6;
            int ii = idx & 63;
            As[kk][ii] = fmaxf(fmaf(xs[ii], us[k0 + kk], cs[k0 + kk]), 0.f);
        }
#pragma unroll
        for (int s = 0; s < 16; s++) {          // Bs: 2048 elems
            int idx = tid + s * 128;
            int kk = idx >> 7;
            int ii = idx & 127;
            Bs[kk][ii] = w2[(k0 + kk) * HDIM + j0 + ii];
        }
        __syncthreads();
#pragma unroll
        for (int kk = 0; kk < 16; kk++) {
            float4 a0 = *reinterpret_cast<const float4*>(&As[kk][ty * 8]);
            float4 a1 = *reinterpret_cast<const float4*>(&As[kk][ty * 8 + 4]);
            float4 b0v = *reinterpret_cast<const float4*>(&Bs[kk][tx * 8]);
            float4 b1v = *reinterpret_cast<const float4*>(&Bs[kk][tx * 8 + 4]);
            float a[8] = {a0.x, a0.y, a0.z, a0.w, a1.x, a1.y, a1.z, a1.w};
            float b[8] = {b0v.x, b0v.y, b0v.z, b0v.w, b1v.x, b1v.y, b1v.z, b1v.w};
#pragma unroll
            for (int m = 0; m < 8; m++)
#pragma unroll
                for (int nn = 0; nn < 8; nn++)
                    acc[m][nn] = fmaf(a[m], b[nn], acc[m][nn]);
        }
        __syncthreads();
    }

    float bb[8];
#pragma unroll
    for (int nn = 0; nn < 8; nn++) bb[nn] = b2[j0 + tx * 8 + nn];
#pragma unroll
    for (int m = 0; m < 8; m++) {
        int row = i0 + ty * 8 + m;
        if (row < nrows) {
#pragma unroll
            for (int nn = 0; nn < 8; nn++)
                g_H2[row * HDIM + j0 + tx * 8 + nn] = fmaxf(acc[m][nn] + bb[nn], 0.f);
        }
    }
}

// ============================================================================
// kT2: A table.  Atab = H2tab @ M + m0.  128x64 tile, BK=16, 8x4 microtile.
// ============================================================================
__global__ void __launch_bounds__(256) kT2_atab(int nrows)
{
    __shared__ float As[16][132];   // 16B-aligned padded stride
    __shared__ float Bs[16][64];

    const int i0 = blockIdx.x * 128;
    const int tid = threadIdx.x;
    const int tx = tid & 15;
    const int ty = tid >> 4;

    float acc[8][4];
#pragma unroll
    for (int m = 0; m < 8; m++)
#pragma unroll
        for (int j = 0; j < 4; j++) acc[m][j] = 0.f;

    for (int k0 = 0; k0 < HDIM; k0 += 16) {
#pragma unroll
        for (int s = 0; s < 2; s++) {
            int e = tid * 2 + s;
            int ii = e >> 2;
            int k4 = e & 3;
            float4 v = *reinterpret_cast<const float4*>(&g_H2[(i0 + ii) * HDIM + k0 + k4 * 4]);
            As[k4 * 4 + 0][ii] = v.x;
            As[k4 * 4 + 1][ii] = v.y;
            As[k4 * 4 + 2][ii] = v.z;
            As[k4 * 4 + 3][ii] = v.w;
        }
#pragma unroll
        for (int s = 0; s < 4; s++) {
            int e = tid + s * 256;
            int kk = e >> 6, jj = e & 63;
            Bs[kk][jj] = g_M[(k0 + kk) * 64 + jj];
        }
        __syncthreads();
#pragma unroll
        for (int kk = 0; kk < 16; kk++) {
            float4 a0 = *reinterpret_cast<const float4*>(&As[kk][ty * 8]);
            float4 a1 = *reinterpret_cast<const float4*>(&As[kk][ty * 8 + 4]);
            float4 bv = *reinterpret_cast<const float4*>(&Bs[kk][tx * 4]);
            float a[8] = {a0.x, a0.y, a0.z, a0.w, a1.x, a1.y, a1.z, a1.w};
            float b[4] = {bv.x, bv.y, bv.z, bv.w};
#pragma unroll
            for (int m = 0; m < 8; m++)
#pragma unroll
                for (int j = 0; j < 4; j++)
                    acc[m][j] = fmaf(a[m], b[j], acc[m][j]);
        }
        __syncthreads();
    }

#pragma unroll
    for (int m = 0; m < 8; m++) {
        int row = i0 + ty * 8 + m;
        if (row < nrows) {
#pragma unroll
            for (int j = 0; j < 4; j++)
                g_Atab[row * 64 + tx * 4 + j] = acc[m][j] + g_m0[tx * 4 + j];
        }
    }
}

// ============================================================================
// k3: CPAB integration with ON-DEMAND per-cell lerp from the L2-resident
//     table (1 MB at GTAB=4096). Integration visits only ~3-6 cells before
//     the exact fixpoint exit, so fetching per-cell (2x float2 per row pair)
//     beats staging all 64 columns. No shared memory -> occupancy regs-bound.
//     Lerp formula identical to before: fmaf(fr, v1-v0, v0).
// ============================================================================
__global__ void __launch_bounds__(256) k3_integrate(const float* __restrict__ x,
                                                    float* __restrict__ out, int n)
{
    const int ip = blockIdx.x * 256 + threadIdx.x;
    if (ip >= n) return;

    float x1 = x[2 * ip + 1];
    x1 = fminf(fmaxf(x1, EPSF), 1.0f - EPSF);
    float f = x1 * (float)GTAB;
    int r = (int)f;
    r = max(0, min(r, GTAB - 1));
    float fr = f - (float)r;
    const float2* row0 = reinterpret_cast<const float2*>(&g_Atab[r * 64]);
    const float2* row1 = reinterpret_cast<const float2*>(&g_Atab[(r + 1) * 64]);

    float x2 = x[2 * ip];
    float xc = fminf(fmaxf(x2, EPSF), 1.0f - EPSF);
    float t = 1.0f;
    float S = 0.0f;
    const float inv = 1.0f / (float)NCELL;
    const float INF = __int_as_float(0x7f800000);

#pragma unroll 1
    for (int it = 0; it < NCELL + 2; it++) {
        int c = (int)(xc * (float)NCELL);
        c = max(0, min(c, NCELL - 1));
        float2 p0 = __ldg(&row0[c]);
        float2 p1 = __ldg(&row1[c]);
        float a = fmaf(fr, p1.x - p0.x, p0.x);
        float b = fmaf(fr, p1.y - p0.y, p0.y);
        float v = a * xc + b;
        float xbnd = ((v >= 0.f) ? (float)(c + 1) : (float)c) * inv;
        bool  small_a = fabsf(a) < TINYF;
        float safe_a = small_a ? 1.0f : a;
        float e = b / safe_a;                       // precise: drives drift matching
        float denom = xc + e;
        float safe_denom = (fabsf(denom) < TINYF) ? ((denom >= 0.f) ? TINYF : -TINYF) : denom;
        float ratio = __fdividef(xbnd + e, safe_denom);
        float thit_exp = __fdividef(__logf(fmaxf(ratio, TINYF)), safe_a);
        float safe_b = (fabsf(b) < TINYF) ? TINYF : b;
        float thit_lin = __fdividef(xbnd - xc, safe_b);
        float thit = small_a ? thit_lin : ((ratio > TINYF) ? thit_exp : INF);
        thit = (thit <= 0.f) ? INF : thit;
        float dt = fminf(thit, t);
        bool cross = (thit <= t);
        float x_exp = (xc + e) * __expf(a * dt) - e;
        float x_lin = xc + b * dt;
        float xn = small_a ? x_lin : x_exp;
        float nudge = (v >= 0.f) ? 1e-7f : -1e-7f;
        xn = cross ? (xbnd + nudge) : xn;
        xn = fminf(fmaxf(xn, EPSF), 1.0f - EPSF);
        S += a * dt;
        t = t - dt;
        bool done = (dt == 0.0f) && (xn == xc);     // exact fixpoint
        xc = xn;
        if (__all_sync(0xffffffffu, done)) break;
    }

    out[2 * ip]     = xc;
    out[2 * ip + 1] = x1;
    out[2 * n + 2 * ip]     = S;
    out[2 * n + 2 * ip + 1] = 0.0f;
}

// ============================================================================
extern "C" void kernel_launch(void* const* d_in, const int* in_sizes, int n_in,
                              void* d_out, int out_size)
{
    const float* x  = (const float*)d_in[0];
    const float* w0 = (const float*)d_in[1];
    const float* b0 = (const float*)d_in[2];
    const float* w1 = (const float*)d_in[3];
    const float* b1 = (const float*)d_in[4];
    const float* w2 = (const float*)d_in[5];
    const float* b2 = (const float*)d_in[6];
    const float* w3 = (const float*)d_in[7];
    const float* b3 = (const float*)d_in[8];
    float* out = (float*)d_out;

    int n = in_sizes[0] / 2;
    const int nrows = GTAB + 1;

    k0_prep<<<1, 1024>>>(w0, b0, w1, b1, w3, b3);

    dim3 g1((nrows + 63) / 64, 2);
    kT1_h2tab<<<g1, 128>>>(w2, b2, nrows);

    kT2_atab<<<(nrows + 127) / 128, 256>>>(nrows);

    k3_integrate<<<(n + 255) / 256, 256>>>(x, out, n);
}

// round 7
// speedup vs baseline: 31.7790x; 1.8925x over previous
#include <cuda_runtime.h>
#include <math.h>
#include <string.h>

#define HDIM   256
#define NCELL  32
#define DTH    31
#define EPSF   1e-7f
#define TINYF  1e-10f
#define GTAB   2048                  // table cells; nodes = GTAB+1

// ---------------- device scratch (no cudaMalloc allowed) ----------------
__device__ float g_Bmat[DTH * 64];          // host-computed basis, [d][j]
__device__ float g_u[HDIM];
__device__ float g_c[HDIM];
__device__ float g_M[HDIM * 64];            // w3 @ B^T   [256][64]
__device__ float g_m0[64];                  // b3 @ B^T
__device__ float g_H2[(GTAB + 256) * HDIM]; // h2 table (+pad rows)
__device__ float g_Atab[(GTAB + 2) * 64];   // A table rows

// ============================================================================
// Host: numpy SVD null-space basis B = Vt[33:].T via Householder LQ
// (dgesdd Path 4t: dgelqf + dorglq — rows 33..63 of the LQ Q-factor are
// exactly Vt[33:]). Depends only on NC=32, no runtime inputs -> host fp64.
// ============================================================================
static void compute_basis_host(float* Bout /* [DTH][64] */)
{
    static double L[33][64];
    static double Bm[DTH][64];
    static double tau[33];
    memset(L, 0, sizeof(L));
    memset(Bm, 0, sizeof(Bm));

    for (int i = 1; i < NCELL; i++) {
        double xi = (double)i / (double)NCELL;
        L[i - 1][2 * (i - 1)]     = xi;
        L[i - 1][2 * (i - 1) + 1] = 1.0;
        L[i - 1][2 * i]           = -xi;
        L[i - 1][2 * i + 1]       = -1.0;
    }
    L[NCELL - 1][1]               = 1.0;
    L[NCELL][2 * (NCELL - 1)]     = 1.0;
    L[NCELL][2 * (NCELL - 1) + 1] = 1.0;

    // dgelqf
    for (int i = 0; i < 33; i++) {
        double xn2 = 0.0;
        for (int j = i + 1; j < 64; j++) xn2 += L[i][j] * L[i][j];
        if (xn2 == 0.0) { tau[i] = 0.0; continue; }
        double alpha = L[i][i];
        double beta = sqrt(alpha * alpha + xn2);
        beta = (alpha >= 0.0) ? -beta : beta;
        tau[i] = (beta - alpha) / beta;
        double sc = 1.0 / (alpha - beta);
        for (int j = i + 1; j < 64; j++) L[i][j] *= sc;
        L[i][i] = beta;
        for (int r = i + 1; r < 33; r++) {
            double w = L[r][i];
            for (int j = i + 1; j < 64; j++) w += L[r][j] * L[i][j];
            w *= tau[i];
            L[r][i] -= w;
            for (int j = i + 1; j < 64; j++) L[r][j] -= w * L[i][j];
        }
    }
    // dorglq rows 33..63: E = [0 | I_31], apply H(32)..H(0) on the right
    for (int r = 0; r < DTH; r++) Bm[r][33 + r] = 1.0;
    for (int i = 32; i >= 0; i--) {
        if (tau[i] == 0.0) continue;
        for (int r = 0; r < DTH; r++) {
            double w = Bm[r][i];
            for (int j = i + 1; j < 64; j++) w += Bm[r][j] * L[i][j];
            w *= tau[i];
            Bm[r][i] -= w;
            for (int j = i + 1; j < 64; j++) Bm[r][j] -= w * L[i][j];
        }
    }
    for (int d = 0; d < DTH; d++)
        for (int j = 0; j < 64; j++)
            Bout[d * 64 + j] = (float)Bm[d][j];   // Bm[d][j] == B[j][d]
}

// ============================================================================
// k0: fp32 constant folding only.
//     u = w0@w1, c = b0@w1 + b1 (layers 0+1 collapse), M = w3@B^T, m0 = b3@B^T.
// ============================================================================
__global__ void __launch_bounds__(1024) k0_fold(
    const float* __restrict__ w0, const float* __restrict__ b0,
    const float* __restrict__ w1, const float* __restrict__ b1,
    const float* __restrict__ w3, const float* __restrict__ b3)
{
    const int tid = threadIdx.x;
    if (tid < HDIM) {
        float uu = 0.f, cc = 0.f;
        for (int k = 0; k < HDIM; k++) {
            float wv = w1[k * HDIM + tid];
            uu = fmaf(w0[k], wv, uu);
            cc = fmaf(b0[k], wv, cc);
        }
        g_u[tid] = uu;
        g_c[tid] = cc + b1[tid];
    }
    for (int idx = tid; idx < HDIM * 64; idx += 1024) {
        int k = idx >> 6, j = idx & 63;
        float s = 0.f;
        for (int d = 0; d < DTH; d++)
            s = fmaf(w3[k * DTH + d], g_Bmat[d * 64 + j], s);
        g_M[idx] = s;
    }
    if (tid < 64) {
        float s = 0.f;
        for (int d = 0; d < DTH; d++)
            s = fmaf(b3[d], g_Bmat[d * 64 + tid], s);
        g_m0[tid] = s;
    }
}

// ============================================================================
// kT1: h2 table.  H2[g] = relu( relu(x_g*u + c) @ w2 + b2 ), x_g = g/GTAB.
//      64x128 tile, BK=16, 256 threads, 4x8 microtile (8192 FMA/thread).
// ============================================================================
__global__ void __launch_bounds__(256) kT1_h2tab(const float* __restrict__ w2,
                                                 const float* __restrict__ b2, int nrows)
{
    __shared__ float As[16][64];
    __shared__ float Bs[16][128];
    __shared__ float xs[64];
    __shared__ float us[HDIM], cs[HDIM];

    const int i0 = blockIdx.x * 64;
    const int j0 = blockIdx.y * 128;
    const int tid = threadIdx.x;

    us[tid] = g_u[tid];
    cs[tid] = g_c[tid];
    if (tid < 64)
        xs[tid] = (float)(i0 + tid) * (1.0f / (float)GTAB);
    __syncthreads();

    const int tx = tid & 15;          // 16 col groups of 8
    const int ty = tid >> 4;          // 16 row groups of 4

    float acc[4][8];
#pragma unroll
    for (int m = 0; m < 4; m++)
#pragma unroll
        for (int nn = 0; nn < 8; nn++) acc[m][nn] = 0.f;

    for (int k0 = 0; k0 < HDIM; k0 += 16) {
#pragma unroll
        for (int s = 0; s < 4; s++) {           // As: 1024 elems
            int idx = tid + s * 256;
            int kk = idx >> 6;
            int ii = idx & 63;
            As[kk][ii] = fmaxf(fmaf(xs[ii], us[k0 + kk], cs[k0 + kk]), 0.f);
        }
#pragma unroll
        for (int s = 0; s < 8; s++) {           // Bs: 2048 elems
            int idx = tid + s * 256;
            int kk = idx >> 7;
            int ii = idx & 127;
            Bs[kk][ii] = w2[(k0 + kk) * HDIM + j0 + ii];
        }
        __syncthreads();
#pragma unroll
        for (int kk = 0; kk < 16; kk++) {
            float4 a4 = *reinterpret_cast<const float4*>(&As[kk][ty * 4]);
            float4 b0v = *reinterpret_cast<const float4*>(&Bs[kk][tx * 8]);
            float4 b1v = *reinterpret_cast<const float4*>(&Bs[kk][tx * 8 + 4]);
            float a[4] = {a4.x, a4.y, a4.z, a4.w};
            float b[8] = {b0v.x, b0v.y, b0v.z, b0v.w, b1v.x, b1v.y, b1v.z, b1v.w};
#pragma unroll
            for (int m = 0; m < 4; m++)
#pragma unroll
                for (int nn = 0; nn < 8; nn++)
                    acc[m][nn] = fmaf(a[m], b[nn], acc[m][nn]);
        }
        __syncthreads();
    }

    float bb[8];
#pragma unroll
    for (int nn = 0; nn < 8; nn++) bb[nn] = b2[j0 + tx * 8 + nn];
#pragma unroll
    for (int m = 0; m < 4; m++) {
        int row = i0 + ty * 4 + m;
        if (row < nrows) {
#pragma unroll
            for (int nn = 0; nn < 8; nn++)
                g_H2[row * HDIM + j0 + tx * 8 + nn] = fmaxf(acc[m][nn] + bb[nn], 0.f);
        }
    }
}

// ============================================================================
// kT2: A table.  Atab = H2tab @ M + m0.  64x64 tile, BK=16, 256 threads,
//      4x4 microtile (4096 FMA/thread).
// ============================================================================
__global__ void __launch_bounds__(256) kT2_atab(int nrows)
{
    __shared__ float As[16][68];    // stride 272 B = 17x16 -> float4-aligned
    __shared__ float Bs[16][64];

    const int i0 = blockIdx.x * 64;
    const int tid = threadIdx.x;
    const int tx = tid & 15;        // 16 col groups of 4
    const int ty = tid >> 4;        // 16 row groups of 4

    float acc[4][4];
#pragma unroll
    for (int m = 0; m < 4; m++)
#pragma unroll
        for (int j = 0; j < 4; j++) acc[m][j] = 0.f;

    for (int k0 = 0; k0 < HDIM; k0 += 16) {
        {
            int e = tid;                  // 256 float4 units: 64 rows x 4
            int ii = e >> 2;
            int k4 = e & 3;
            float4 v = *reinterpret_cast<const float4*>(&g_H2[(i0 + ii) * HDIM + k0 + k4 * 4]);
            As[k4 * 4 + 0][ii] = v.x;
            As[k4 * 4 + 1][ii] = v.y;
            As[k4 * 4 + 2][ii] = v.z;
            As[k4 * 4 + 3][ii] = v.w;
        }
#pragma unroll
        for (int s = 0; s < 4; s++) {
            int e = tid + s * 256;
            int kk = e >> 6, jj = e & 63;
            Bs[kk][jj] = g_M[(k0 + kk) * 64 + jj];
        }
        __syncthreads();
#pragma unroll
        for (int kk = 0; kk < 16; kk++) {
            float4 a4 = *reinterpret_cast<const float4*>(&As[kk][ty * 4]);
            float4 b4 = *reinterpret_cast<const float4*>(&Bs[kk][tx * 4]);
            float a[4] = {a4.x, a4.y, a4.z, a4.w};
            float b[4] = {b4.x, b4.y, b4.z, b4.w};
#pragma unroll
            for (int m = 0; m < 4; m++)
#pragma unroll
                for (int j = 0; j < 4; j++)
                    acc[m][j] = fmaf(a[m], b[j], acc[m][j]);
        }
        __syncthreads();
    }

#pragma unroll
    for (int m = 0; m < 4; m++) {
        int row = i0 + ty * 4 + m;
        if (row < nrows) {
#pragma unroll
            for (int j = 0; j < 4; j++)
                g_Atab[row * 64 + tx * 4 + j] = acc[m][j] + g_m0[tx * 4 + j];
        }
    }
}

// ============================================================================
// k3: CPAB integration with on-demand per-cell lerp from the L2-resident
//     table. Exact fixpoint early-exit; fast intrinsics on crossing math,
//     precise '/' kept for e=b/a (drives reference-matching drift).
// ============================================================================
__global__ void __launch_bounds__(256) k3_integrate(const float* __restrict__ x,
                                                    float* __restrict__ out, int n)
{
    const int ip = blockIdx.x * 256 + threadIdx.x;
    if (ip >= n) return;

    float x1 = x[2 * ip + 1];
    x1 = fminf(fmaxf(x1, EPSF), 1.0f - EPSF);
    float f = x1 * (float)GTAB;
    int r = (int)f;
    r = max(0, min(r, GTAB - 1));
    float fr = f - (float)r;
    const float2* row0 = reinterpret_cast<const float2*>(&g_Atab[r * 64]);
    const float2* row1 = reinterpret_cast<const float2*>(&g_Atab[(r + 1) * 64]);

    float x2 = x[2 * ip];
    float xc = fminf(fmaxf(x2, EPSF), 1.0f - EPSF);
    float t = 1.0f;
    float S = 0.0f;
    const float inv = 1.0f / (float)NCELL;
    const float INF = __int_as_float(0x7f800000);

#pragma unroll 1
    for (int it = 0; it < NCELL + 2; it++) {
        int c = (int)(xc * (float)NCELL);
        c = max(0, min(c, NCELL - 1));
        float2 p0 = __ldg(&row0[c]);
        float2 p1 = __ldg(&row1[c]);
        float a = fmaf(fr, p1.x - p0.x, p0.x);
        float b = fmaf(fr, p1.y - p0.y, p0.y);
        float v = a * xc + b;
        float xbnd = ((v >= 0.f) ? (float)(c + 1) : (float)c) * inv;
        bool  small_a = fabsf(a) < TINYF;
        float safe_a = small_a ? 1.0f : a;
        float e = b / safe_a;                       // precise: drives drift matching
        float denom = xc + e;
        float safe_denom = (fabsf(denom) < TINYF) ? ((denom >= 0.f) ? TINYF : -TINYF) : denom;
        float ratio = __fdividef(xbnd + e, safe_denom);
        float thit_exp = __fdividef(__logf(fmaxf(ratio, TINYF)), safe_a);
        float safe_b = (fabsf(b) < TINYF) ? TINYF : b;
        float thit_lin = __fdividef(xbnd - xc, safe_b);
        float thit = small_a ? thit_lin : ((ratio > TINYF) ? thit_exp : INF);
        thit = (thit <= 0.f) ? INF : thit;
        float dt = fminf(thit, t);
        bool cross = (thit <= t);
        float x_exp = (xc + e) * __expf(a * dt) - e;
        float x_lin = xc + b * dt;
        float xn = small_a ? x_lin : x_exp;
        float nudge = (v >= 0.f) ? 1e-7f : -1e-7f;
        xn = cross ? (xbnd + nudge) : xn;
        xn = fminf(fmaxf(xn, EPSF), 1.0f - EPSF);
        S += a * dt;
        t = t - dt;
        bool done = (dt == 0.0f) && (xn == xc);     // exact fixpoint
        xc = xn;
        if (__all_sync(0xffffffffu, done)) break;
    }

    out[2 * ip]     = xc;
    out[2 * ip + 1] = x1;
    out[2 * n + 2 * ip]     = S;
    out[2 * n + 2 * ip + 1] = 0.0f;
}

// ============================================================================
static float s_Bhost[DTH * 64];   // persists across graph replays

extern "C" void kernel_launch(void* const* d_in, const int* in_sizes, int n_in,
                              void* d_out, int out_size)
{
    const float* x  = (const float*)d_in[0];
    const float* w0 = (const float*)d_in[1];
    const float* b0 = (const float*)d_in[2];
    const float* w1 = (const float*)d_in[3];
    const float* b1 = (const float*)d_in[4];
    const float* w2 = (const float*)d_in[5];
    const float* b2 = (const float*)d_in[6];
    const float* w3 = (const float*)d_in[7];
    const float* b3 = (const float*)d_in[8];
    float* out = (float*)d_out;

    int n = in_sizes[0] / 2;
    const int nrows = GTAB + 1;

    compute_basis_host(s_Bhost);    // input-independent, deterministic
    cudaMemcpyToSymbolAsync(g_Bmat, s_Bhost, sizeof(s_Bhost), 0,
                            cudaMemcpyHostToDevice, 0);

    k0_fold<<<1, 1024>>>(w0, b0, w1, b1, w3, b3);

    dim3 g1((nrows + 63) / 64, 2);
    kT1_h2tab<<<g1, 256>>>(w2, b2, nrows);

    kT2_atab<<<(nrows + 63) / 64, 256>>>(nrows);

    k3_integrate<<<(n + 255) / 256, 256>>>(x, out, n);
}

// round 8
// speedup vs baseline: 45.2447x; 1.4237x over previous
#include <cuda_runtime.h>
#include <math.h>
#include <string.h>

#define HDIM   256
#define NCELL  32
#define DTH    31
#define EPSF   1e-7f
#define TINYF  1e-10f
#define GTAB   1024                  // table cells; nodes = GTAB+1

// ---------------- device scratch (no cudaMalloc allowed) ----------------
__device__ float g_Bmat[DTH * 64];          // host-computed basis, [d][j]
__device__ float g_H2[(GTAB + 64) * HDIM];  // h2 table (+pad rows)
__device__ float g_Atab[(GTAB + 2) * 64];   // A table rows

// ============================================================================
// Host: numpy SVD null-space basis B = Vt[33:].T via Householder LQ
// (dgesdd Path 4t: dgelqf + dorglq — rows 33..63 of the LQ Q-factor are
// exactly Vt[33:]). Depends only on NC=32, no runtime inputs -> host fp64.
// ============================================================================
static void compute_basis_host(float* Bout /* [DTH][64] */)
{
    static double L[33][64];
    static double Bm[DTH][64];
    static double tau[33];
    memset(L, 0, sizeof(L));
    memset(Bm, 0, sizeof(Bm));

    for (int i = 1; i < NCELL; i++) {
        double xi = (double)i / (double)NCELL;
        L[i - 1][2 * (i - 1)]     = xi;
        L[i - 1][2 * (i - 1) + 1] = 1.0;
        L[i - 1][2 * i]           = -xi;
        L[i - 1][2 * i + 1]       = -1.0;
    }
    L[NCELL - 1][1]               = 1.0;
    L[NCELL][2 * (NCELL - 1)]     = 1.0;
    L[NCELL][2 * (NCELL - 1) + 1] = 1.0;

    for (int i = 0; i < 33; i++) {
        double xn2 = 0.0;
        for (int j = i + 1; j < 64; j++) xn2 += L[i][j] * L[i][j];
        if (xn2 == 0.0) { tau[i] = 0.0; continue; }
        double alpha = L[i][i];
        double beta = sqrt(alpha * alpha + xn2);
        beta = (alpha >= 0.0) ? -beta : beta;
        tau[i] = (beta - alpha) / beta;
        double sc = 1.0 / (alpha - beta);
        for (int j = i + 1; j < 64; j++) L[i][j] *= sc;
        L[i][i] = beta;
        for (int r = i + 1; r < 33; r++) {
            double w = L[r][i];
            for (int j = i + 1; j < 64; j++) w += L[r][j] * L[i][j];
            w *= tau[i];
            L[r][i] -= w;
            for (int j = i + 1; j < 64; j++) L[r][j] -= w * L[i][j];
        }
    }
    for (int r = 0; r < DTH; r++) Bm[r][33 + r] = 1.0;
    for (int i = 32; i >= 0; i--) {
        if (tau[i] == 0.0) continue;
        for (int r = 0; r < DTH; r++) {
            double w = Bm[r][i];
            for (int j = i + 1; j < 64; j++) w += Bm[r][j] * L[i][j];
            w *= tau[i];
            Bm[r][i] -= w;
            for (int j = i + 1; j < 64; j++) Bm[r][j] -= w * L[i][j];
        }
    }
    for (int d = 0; d < DTH; d++)
        for (int j = 0; j < 64; j++)
            Bout[d * 64 + j] = (float)Bm[d][j];
}

// ============================================================================
// kT1: h2 table with INLINE u,c fold.
//      H2[g] = relu( relu(x_g*u + c) @ w2 + b2 ), x_g = g/GTAB,
//      u = w0@w1, c = b0@w1 + b1 (each block recomputes; parallel, L2-fed).
//      32x64 tile, BK=16, 256 threads, 4x2 microtile (2048 FMA/thread).
// ============================================================================
__global__ void __launch_bounds__(256) kT1_h2tab(
    const float* __restrict__ w0, const float* __restrict__ b0,
    const float* __restrict__ w1, const float* __restrict__ b1,
    const float* __restrict__ w2, const float* __restrict__ b2, int nrows)
{
    __shared__ float us[HDIM], cs[HDIM];
    __shared__ float xs[32];
    __shared__ float As[16][36];   // stride 144B (16B-aligned)
    __shared__ float Bs[16][64];

    const int i0 = blockIdx.x * 32;
    const int j0 = blockIdx.y * 64;
    const int tid = threadIdx.x;

    // inline u,c fold: thread tid computes u[tid], c[tid]
    {
        float uu = 0.f, cc = 0.f;
#pragma unroll 4
        for (int k = 0; k < HDIM; k++) {
            float wv = w1[k * HDIM + tid];
            uu = fmaf(w0[k], wv, uu);
            cc = fmaf(b0[k], wv, cc);
        }
        us[tid] = uu;
        cs[tid] = cc + b1[tid];
    }
    if (tid < 32)
        xs[tid] = (float)(i0 + tid) * (1.0f / (float)GTAB);
    __syncthreads();

    const int tx = tid & 31;       // 32 col groups of 2
    const int ty = tid >> 5;       // 8 row groups of 4

    float acc[4][2];
#pragma unroll
    for (int m = 0; m < 4; m++) { acc[m][0] = 0.f; acc[m][1] = 0.f; }

    for (int k0 = 0; k0 < HDIM; k0 += 16) {
#pragma unroll
        for (int s = 0; s < 2; s++) {           // As: 512 elems
            int e = tid + s * 256;
            int kk = e >> 5, ii = e & 31;
            As[kk][ii] = fmaxf(fmaf(xs[ii], us[k0 + kk], cs[k0 + kk]), 0.f);
        }
#pragma unroll
        for (int s = 0; s < 4; s++) {           // Bs: 1024 elems
            int e = tid + s * 256;
            int kk = e >> 6, jj = e & 63;
            Bs[kk][jj] = w2[(k0 + kk) * HDIM + j0 + jj];
        }
        __syncthreads();
#pragma unroll
        for (int kk = 0; kk < 16; kk++) {
            float4 a4 = *reinterpret_cast<const float4*>(&As[kk][ty * 4]);
            float2 bv = *reinterpret_cast<const float2*>(&Bs[kk][tx * 2]);
            float a[4] = {a4.x, a4.y, a4.z, a4.w};
#pragma unroll
            for (int m = 0; m < 4; m++) {
                acc[m][0] = fmaf(a[m], bv.x, acc[m][0]);
                acc[m][1] = fmaf(a[m], bv.y, acc[m][1]);
            }
        }
        __syncthreads();
    }

    float bb0 = b2[j0 + tx * 2];
    float bb1 = b2[j0 + tx * 2 + 1];
#pragma unroll
    for (int m = 0; m < 4; m++) {
        int row = i0 + ty * 4 + m;
        if (row < nrows) {
            float2 v;
            v.x = fmaxf(acc[m][0] + bb0, 0.f);
            v.y = fmaxf(acc[m][1] + bb1, 0.f);
            *reinterpret_cast<float2*>(&g_H2[row * HDIM + j0 + tx * 2]) = v;
        }
    }
}

// ============================================================================
// kT2: A table directly:  A = (H2 @ w3 + b3) @ B^T.
//      Reassociated (DTH=31 inner dim) -> no M precompute needed.
//      32 rows/block, 256 threads. smem ~45 KB.
// ============================================================================
__global__ void __launch_bounds__(256) kT2_atab(
    const float* __restrict__ w3, const float* __restrict__ b3, int nrows)
{
    __shared__ float H2s[256][33];   // [k][i], 33.8 KB
    __shared__ float Ts[32][33];     // [d][i] (+b3 folded), 4.2 KB
    __shared__ float Bs[DTH][64];    // basis, 7.9 KB

    const int i0 = blockIdx.x * 32;
    const int tid = threadIdx.x;

    // stage H2 tile (transposed), coalesced float4 reads
#pragma unroll
    for (int s = 0; s < 8; s++) {
        int e = tid + s * 256;           // 0..2047 float4 units
        int i = e >> 6, kq = e & 63;
        float4 v = *reinterpret_cast<const float4*>(&g_H2[(i0 + i) * HDIM + kq * 4]);
        H2s[kq * 4 + 0][i] = v.x;
        H2s[kq * 4 + 1][i] = v.y;
        H2s[kq * 4 + 2][i] = v.z;
        H2s[kq * 4 + 3][i] = v.w;
    }
    // stage basis
    for (int e = tid; e < DTH * 64; e += 256)
        Bs[e >> 6][e & 63] = g_Bmat[e];
    __syncthreads();

    // T = H2 @ w3  (+ b3):  thread (i, dbase..dbase+3)
    {
        const int i = tid & 31;
        const int dbase = (tid >> 5) * 4;    // 0,4,...,28
        float acc[4] = {0.f, 0.f, 0.f, 0.f};
#pragma unroll 4
        for (int k = 0; k < HDIM; k++) {
            float h = H2s[k][i];
#pragma unroll
            for (int q = 0; q < 4; q++) {
                int d = dbase + q;
                if (d < DTH)
                    acc[q] = fmaf(h, __ldg(&w3[k * DTH + d]), acc[q]);
            }
        }
#pragma unroll
        for (int q = 0; q < 4; q++) {
            int d = dbase + q;
            if (d < DTH) Ts[d][i] = acc[q] + b3[d];
        }
    }
    __syncthreads();

    // A = T @ B^T: thread (j, ig): 8 rows each
    {
        const int j = tid & 63;
        const int ig = tid >> 6;             // 0..3
        float acc8[8];
#pragma unroll
        for (int m = 0; m < 8; m++) acc8[m] = 0.f;
#pragma unroll
        for (int d = 0; d < DTH; d++) {
            float bv = Bs[d][j];
#pragma unroll
            for (int m = 0; m < 8; m++)
                acc8[m] = fmaf(Ts[d][ig + m * 4], bv, acc8[m]);
        }
#pragma unroll
        for (int m = 0; m < 8; m++) {
            int row = i0 + ig + m * 4;
            if (row < nrows)
                g_Atab[row * 64 + j] = acc8[m];
        }
    }
}

// ============================================================================
// k3: CPAB integration, 2 points/thread (float4 I/O, two interleaved latency
//     chains). On-demand per-cell lerp from L2-resident table; exact fixpoint
//     early-exit; fast intrinsics except precise '/' for e=b/a.
// ============================================================================
__global__ void __launch_bounds__(256) k3_integrate(const float* __restrict__ x,
                                                    float* __restrict__ out, int n)
{
    const int gt = blockIdx.x * 256 + threadIdx.x;   // pair index
    const int ip0 = 2 * gt;
    const bool v0 = (ip0 < n);
    const bool v1 = (ip0 + 1 < n);

    float x2a = 0.5f, x1a = 0.5f, x2b = 0.5f, x1b = 0.5f;
    if (v1) {
        float4 xv = *reinterpret_cast<const float4*>(&x[2 * ip0]);
        x2a = xv.x; x1a = xv.y; x2b = xv.z; x1b = xv.w;
    } else if (v0) {
        x2a = x[2 * ip0]; x1a = x[2 * ip0 + 1];
    }
    x1a = fminf(fmaxf(x1a, EPSF), 1.0f - EPSF);
    x1b = fminf(fmaxf(x1b, EPSF), 1.0f - EPSF);

    float fa = x1a * (float)GTAB, fb = x1b * (float)GTAB;
    int ra = max(0, min((int)fa, GTAB - 1));
    int rb = max(0, min((int)fb, GTAB - 1));
    float fra = fa - (float)ra, frb = fb - (float)rb;
    const float2* a_r0 = reinterpret_cast<const float2*>(&g_Atab[ra * 64]);
    const float2* a_r1 = reinterpret_cast<const float2*>(&g_Atab[(ra + 1) * 64]);
    const float2* b_r0 = reinterpret_cast<const float2*>(&g_Atab[rb * 64]);
    const float2* b_r1 = reinterpret_cast<const float2*>(&g_Atab[(rb + 1) * 64]);

    float xca = fminf(fmaxf(x2a, EPSF), 1.0f - EPSF);
    float xcb = fminf(fmaxf(x2b, EPSF), 1.0f - EPSF);
    float ta = 1.0f, tb = 1.0f;
    float Sa = 0.0f, Sb = 0.0f;
    const float inv = 1.0f / (float)NCELL;
    const float INF = __int_as_float(0x7f800000);

#pragma unroll 1
    for (int it = 0; it < NCELL + 2; it++) {
        // ---- point A ----
        int ca = max(0, min((int)(xca * (float)NCELL), NCELL - 1));
        float2 pa0 = __ldg(&a_r0[ca]);
        float2 pa1 = __ldg(&a_r1[ca]);
        // ---- point B ----
        int cb = max(0, min((int)(xcb * (float)NCELL), NCELL - 1));
        float2 pb0 = __ldg(&b_r0[cb]);
        float2 pb1 = __ldg(&b_r1[cb]);

        float aa = fmaf(fra, pa1.x - pa0.x, pa0.x);
        float ba = fmaf(fra, pa1.y - pa0.y, pa0.y);
        float ab = fmaf(frb, pb1.x - pb0.x, pb0.x);
        float bb = fmaf(frb, pb1.y - pb0.y, pb0.y);

        float va = aa * xca + ba;
        float vb = ab * xcb + bb;
        float xbnda = ((va >= 0.f) ? (float)(ca + 1) : (float)ca) * inv;
        float xbndb = ((vb >= 0.f) ? (float)(cb + 1) : (float)cb) * inv;
        bool sma = fabsf(aa) < TINYF;
        bool smb = fabsf(ab) < TINYF;
        float safa = sma ? 1.0f : aa;
        float safb = smb ? 1.0f : ab;
        float ea = ba / safa;
        float eb = bb / safb;
        float dena = xca + ea, denb = xcb + eb;
        float sdena = (fabsf(dena) < TINYF) ? ((dena >= 0.f) ? TINYF : -TINYF) : dena;
        float sdenb = (fabsf(denb) < TINYF) ? ((denb >= 0.f) ? TINYF : -TINYF) : denb;
        float rata = __fdividef(xbnda + ea, sdena);
        float ratb = __fdividef(xbndb + eb, sdenb);
        float thea = __fdividef(__logf(fmaxf(rata, TINYF)), safa);
        float theb = __fdividef(__logf(fmaxf(ratb, TINYF)), safb);
        float sba = (fabsf(ba) < TINYF) ? TINYF : ba;
        float sbb = (fabsf(bb) < TINYF) ? TINYF : bb;
        float thla = __fdividef(xbnda - xca, sba);
        float thlb = __fdividef(xbndb - xcb, sbb);
        float tha = sma ? thla : ((rata > TINYF) ? thea : INF);
        float thb = smb ? thlb : ((ratb > TINYF) ? theb : INF);
        tha = (tha <= 0.f) ? INF : tha;
        thb = (thb <= 0.f) ? INF : thb;
        float dta = fminf(tha, ta), dtb = fminf(thb, tb);
        bool cra = (tha <= ta), crb = (thb <= tb);
        float xea = (xca + ea) * __expf(aa * dta) - ea;
        float xeb = (xcb + eb) * __expf(ab * dtb) - eb;
        float xla = xca + ba * dta, xlb = xcb + bb * dtb;
        float xna = sma ? xla : xea;
        float xnb = smb ? xlb : xeb;
        float nga = (va >= 0.f) ? 1e-7f : -1e-7f;
        float ngb = (vb >= 0.f) ? 1e-7f : -1e-7f;
        xna = cra ? (xbnda + nga) : xna;
        xnb = crb ? (xbndb + ngb) : xnb;
        xna = fminf(fmaxf(xna, EPSF), 1.0f - EPSF);
        xnb = fminf(fmaxf(xnb, EPSF), 1.0f - EPSF);
        Sa += aa * dta;  Sb += ab * dtb;
        ta -= dta;       tb -= dtb;
        bool done = (dta == 0.0f) && (xna == xca) &&
                    (dtb == 0.0f) && (xnb == xcb);
        xca = xna; xcb = xnb;
        if (__all_sync(0xffffffffu, done)) break;
    }

    if (v1) {
        float4 z; z.x = xca; z.y = x1a; z.z = xcb; z.w = x1b;
        *reinterpret_cast<float4*>(&out[2 * ip0]) = z;
        float4 g; g.x = Sa; g.y = 0.0f; g.z = Sb; g.w = 0.0f;
        *reinterpret_cast<float4*>(&out[2 * n + 2 * ip0]) = g;
    } else if (v0) {
        out[2 * ip0]     = xca;
        out[2 * ip0 + 1] = x1a;
        out[2 * n + 2 * ip0]     = Sa;
        out[2 * n + 2 * ip0 + 1] = 0.0f;
    }
}

// ============================================================================
static float s_Bhost[DTH * 64];   // persists across graph replays

extern "C" void kernel_launch(void* const* d_in, const int* in_sizes, int n_in,
                              void* d_out, int out_size)
{
    const float* x  = (const float*)d_in[0];
    const float* w0 = (const float*)d_in[1];
    const float* b0 = (const float*)d_in[2];
    const float* w1 = (const float*)d_in[3];
    const float* b1 = (const float*)d_in[4];
    const float* w2 = (const float*)d_in[5];
    const float* b2 = (const float*)d_in[6];
    const float* w3 = (const float*)d_in[7];
    const float* b3 = (const float*)d_in[8];
    float* out = (float*)d_out;

    int n = in_sizes[0] / 2;
    const int nrows = GTAB + 1;

    compute_basis_host(s_Bhost);    // input-independent, deterministic
    cudaMemcpyToSymbolAsync(g_Bmat, s_Bhost, sizeof(s_Bhost), 0,
                            cudaMemcpyHostToDevice, 0);

    dim3 g1((nrows + 31) / 32, 4);
    kT1_h2tab<<<g1, 256>>>(w0, b0, w1, b1, w2, b2, nrows);

    kT2_atab<<<(nrows + 31) / 32, 256>>>(w3, b3, nrows);

    int npairs = (n + 1) / 2;
    k3_integrate<<<(npairs + 255) / 256, 256>>>(x, out, n);
}

// round 9
// speedup vs baseline: 54.4783x; 1.2041x over previous
#include <cuda_runtime.h>
#include <math.h>
#include <string.h>

#define HDIM   256
#define NCELL  32
#define DTH    31
#define EPSF   1e-7f
#define TINYF  1e-10f
#define GTAB   1024                  // table cells; nodes = GTAB+1
#define KCH    32                    // k-chunks for u,c partial reduction

// ---------------- device scratch (no cudaMalloc allowed) ----------------
__device__ float g_Bmat[DTH * 64];          // host-computed basis, [d][j]
__device__ float g_upart[KCH * HDIM];       // partial sums of u
__device__ float g_cpart[KCH * HDIM];       // partial sums of c (pre-b1)
__device__ float g_H2[(GTAB + 64) * HDIM];  // h2 table (+pad rows)
__device__ float g_Atab[(GTAB + 2) * 64];   // A table rows

// ============================================================================
// Host: numpy SVD null-space basis B = Vt[33:].T via Householder LQ
// (dgesdd Path 4t: dgelqf + dorglq — rows 33..63 of the LQ Q-factor are
// exactly Vt[33:]). Depends only on NC=32, no runtime inputs -> host fp64.
// ============================================================================
static void compute_basis_host(float* Bout /* [DTH][64] */)
{
    static double L[33][64];
    static double Bm[DTH][64];
    static double tau[33];
    memset(L, 0, sizeof(L));
    memset(Bm, 0, sizeof(Bm));

    for (int i = 1; i < NCELL; i++) {
        double xi = (double)i / (double)NCELL;
        L[i - 1][2 * (i - 1)]     = xi;
        L[i - 1][2 * (i - 1) + 1] = 1.0;
        L[i - 1][2 * i]           = -xi;
        L[i - 1][2 * i + 1]       = -1.0;
    }
    L[NCELL - 1][1]               = 1.0;
    L[NCELL][2 * (NCELL - 1)]     = 1.0;
    L[NCELL][2 * (NCELL - 1) + 1] = 1.0;

    for (int i = 0; i < 33; i++) {
        double xn2 = 0.0;
        for (int j = i + 1; j < 64; j++) xn2 += L[i][j] * L[i][j];
        if (xn2 == 0.0) { tau[i] = 0.0; continue; }
        double alpha = L[i][i];
        double beta = sqrt(alpha * alpha + xn2);
        beta = (alpha >= 0.0) ? -beta : beta;
        tau[i] = (beta - alpha) / beta;
        double sc = 1.0 / (alpha - beta);
        for (int j = i + 1; j < 64; j++) L[i][j] *= sc;
        L[i][i] = beta;
        for (int r = i + 1; r < 33; r++) {
            double w = L[r][i];
            for (int j = i + 1; j < 64; j++) w += L[r][j] * L[i][j];
            w *= tau[i];
            L[r][i] -= w;
            for (int j = i + 1; j < 64; j++) L[r][j] -= w * L[i][j];
        }
    }
    for (int r = 0; r < DTH; r++) Bm[r][33 + r] = 1.0;
    for (int i = 32; i >= 0; i--) {
        if (tau[i] == 0.0) continue;
        for (int r = 0; r < DTH; r++) {
            double w = Bm[r][i];
            for (int j = i + 1; j < 64; j++) w += Bm[r][j] * L[i][j];
            w *= tau[i];
            Bm[r][i] -= w;
            for (int j = i + 1; j < 64; j++) Bm[r][j] -= w * L[i][j];
        }
    }
    for (int d = 0; d < DTH; d++)
        for (int j = 0; j < 64; j++)
            Bout[d * 64 + j] = (float)Bm[d][j];
}

// ============================================================================
// k0u: stage-1 partial reduction of u = w0@w1, c = b0@w1.
//      32 blocks x 256 threads; block b covers k in [8b, 8b+8).
//      Coalesced w1 reads, parallel across SMs (the R8 inline fold was the
//      48us bottleneck: every kT1 block streamed all 256KB of w1 itself).
// ============================================================================
__global__ void __launch_bounds__(256) k0u_part(
    const float* __restrict__ w0, const float* __restrict__ b0,
    const float* __restrict__ w1)
{
    const int tid = threadIdx.x;
    const int b = blockIdx.x;
    float uu = 0.f, cc = 0.f;
#pragma unroll
    for (int kk = 0; kk < HDIM / KCH; kk++) {
        int k = b * (HDIM / KCH) + kk;
        float wv = w1[k * HDIM + tid];
        uu = fmaf(w0[k], wv, uu);
        cc = fmaf(b0[k], wv, cc);
    }
    g_upart[b * HDIM + tid] = uu;
    g_cpart[b * HDIM + tid] = cc;
}

// ============================================================================
// kT1: h2 table.  H2[g] = relu( relu(x_g*u + c) @ w2 + b2 ), x_g = g/GTAB.
//      Per-block u,c: deterministic fixed-order sum of the 32 partials
//      (64 L2 loads/thread, high MLP, ~1us). 32x64 tile, BK=16, 256 threads.
// ============================================================================
__global__ void __launch_bounds__(256) kT1_h2tab(
    const float* __restrict__ b1,
    const float* __restrict__ w2, const float* __restrict__ b2, int nrows)
{
    __shared__ float us[HDIM], cs[HDIM];
    __shared__ float xs[32];
    __shared__ float As[16][36];   // stride 144B (16B-aligned)
    __shared__ float Bs[16][64];

    const int i0 = blockIdx.x * 32;
    const int j0 = blockIdx.y * 64;
    const int tid = threadIdx.x;

    // reduce partials (fixed order -> deterministic)
    {
        float uu = 0.f, cc = 0.f;
#pragma unroll
        for (int b = 0; b < KCH; b++) {
            uu += g_upart[b * HDIM + tid];
            cc += g_cpart[b * HDIM + tid];
        }
        us[tid] = uu;
        cs[tid] = cc + b1[tid];
    }
    if (tid < 32)
        xs[tid] = (float)(i0 + tid) * (1.0f / (float)GTAB);
    __syncthreads();

    const int tx = tid & 31;       // 32 col groups of 2
    const int ty = tid >> 5;       // 8 row groups of 4

    float acc[4][2];
#pragma unroll
    for (int m = 0; m < 4; m++) { acc[m][0] = 0.f; acc[m][1] = 0.f; }

    for (int k0 = 0; k0 < HDIM; k0 += 16) {
#pragma unroll
        for (int s = 0; s < 2; s++) {           // As: 512 elems
            int e = tid + s * 256;
            int kk = e >> 5, ii = e & 31;
            As[kk][ii] = fmaxf(fmaf(xs[ii], us[k0 + kk], cs[k0 + kk]), 0.f);
        }
#pragma unroll
        for (int s = 0; s < 4; s++) {           // Bs: 1024 elems
            int e = tid + s * 256;
            int kk = e >> 6, jj = e & 63;
            Bs[kk][jj] = w2[(k0 + kk) * HDIM + j0 + jj];
        }
        __syncthreads();
#pragma unroll
        for (int kk = 0; kk < 16; kk++) {
            float4 a4 = *reinterpret_cast<const float4*>(&As[kk][ty * 4]);
            float2 bv = *reinterpret_cast<const float2*>(&Bs[kk][tx * 2]);
            float a[4] = {a4.x, a4.y, a4.z, a4.w};
#pragma unroll
            for (int m = 0; m < 4; m++) {
                acc[m][0] = fmaf(a[m], bv.x, acc[m][0]);
                acc[m][1] = fmaf(a[m], bv.y, acc[m][1]);
            }
        }
        __syncthreads();
    }

    float bb0 = b2[j0 + tx * 2];
    float bb1 = b2[j0 + tx * 2 + 1];
#pragma unroll
    for (int m = 0; m < 4; m++) {
        int row = i0 + ty * 4 + m;
        if (row < nrows) {
            float2 v;
            v.x = fmaxf(acc[m][0] + bb0, 0.f);
            v.y = fmaxf(acc[m][1] + bb1, 0.f);
            *reinterpret_cast<float2*>(&g_H2[row * HDIM + j0 + tx * 2]) = v;
        }
    }
}

// ============================================================================
// kT2: A table directly:  A = (H2 @ w3 + b3) @ B^T.
//      Reassociated (DTH=31 inner dim) -> no M precompute needed.
// ============================================================================
__global__ void __launch_bounds__(256) kT2_atab(
    const float* __restrict__ w3, const float* __restrict__ b3, int nrows)
{
    __shared__ float H2s[256][33];   // [k][i], 33.8 KB
    __shared__ float Ts[32][33];     // [d][i] (+b3 folded), 4.2 KB
    __shared__ float Bs[DTH][64];    // basis, 7.9 KB

    const int i0 = blockIdx.x * 32;
    const int tid = threadIdx.x;

    // stage H2 tile (transposed), coalesced float4 reads
#pragma unroll
    for (int s = 0; s < 8; s++) {
        int e = tid + s * 256;           // 0..2047 float4 units
        int i = e >> 6, kq = e & 63;
        float4 v = *reinterpret_cast<const float4*>(&g_H2[(i0 + i) * HDIM + kq * 4]);
        H2s[kq * 4 + 0][i] = v.x;
        H2s[kq * 4 + 1][i] = v.y;
        H2s[kq * 4 + 2][i] = v.z;
        H2s[kq * 4 + 3][i] = v.w;
    }
    for (int e = tid; e < DTH * 64; e += 256)
        Bs[e >> 6][e & 63] = g_Bmat[e];
    __syncthreads();

    // T = H2 @ w3  (+ b3)
    {
        const int i = tid & 31;
        const int dbase = (tid >> 5) * 4;    // 0,4,...,28
        float acc[4] = {0.f, 0.f, 0.f, 0.f};
#pragma unroll 4
        for (int k = 0; k < HDIM; k++) {
            float h = H2s[k][i];
#pragma unroll
            for (int q = 0; q < 4; q++) {
                int d = dbase + q;
                if (d < DTH)
                    acc[q] = fmaf(h, __ldg(&w3[k * DTH + d]), acc[q]);
            }
        }
#pragma unroll
        for (int q = 0; q < 4; q++) {
            int d = dbase + q;
            if (d < DTH) Ts[d][i] = acc[q] + b3[d];
        }
    }
    __syncthreads();

    // A = T @ B^T
    {
        const int j = tid & 63;
        const int ig = tid >> 6;             // 0..3
        float acc8[8];
#pragma unroll
        for (int m = 0; m < 8; m++) acc8[m] = 0.f;
#pragma unroll
        for (int d = 0; d < DTH; d++) {
            float bv = Bs[d][j];
#pragma unroll
            for (int m = 0; m < 8; m++)
                acc8[m] = fmaf(Ts[d][ig + m * 4], bv, acc8[m]);
        }
#pragma unroll
        for (int m = 0; m < 8; m++) {
            int row = i0 + ig + m * 4;
            if (row < nrows)
                g_Atab[row * 64 + j] = acc8[m];
        }
    }
}

// ============================================================================
// k3: CPAB integration, 2 points/thread (float4 I/O, two interleaved latency
//     chains). On-demand per-cell lerp from L2-resident table; exact fixpoint
//     early-exit; fast intrinsics except precise '/' for e=b/a.
// ============================================================================
__global__ void __launch_bounds__(256) k3_integrate(const float* __restrict__ x,
                                                    float* __restrict__ out, int n)
{
    const int gt = blockIdx.x * 256 + threadIdx.x;   // pair index
    const int ip0 = 2 * gt;
    const bool v0 = (ip0 < n);
    const bool v1 = (ip0 + 1 < n);

    float x2a = 0.5f, x1a = 0.5f, x2b = 0.5f, x1b = 0.5f;
    if (v1) {
        float4 xv = *reinterpret_cast<const float4*>(&x[2 * ip0]);
        x2a = xv.x; x1a = xv.y; x2b = xv.z; x1b = xv.w;
    } else if (v0) {
        x2a = x[2 * ip0]; x1a = x[2 * ip0 + 1];
    }
    x1a = fminf(fmaxf(x1a, EPSF), 1.0f - EPSF);
    x1b = fminf(fmaxf(x1b, EPSF), 1.0f - EPSF);

    float fa = x1a * (float)GTAB, fb = x1b * (float)GTAB;
    int ra = max(0, min((int)fa, GTAB - 1));
    int rb = max(0, min((int)fb, GTAB - 1));
    float fra = fa - (float)ra, frb = fb - (float)rb;
    const float2* a_r0 = reinterpret_cast<const float2*>(&g_Atab[ra * 64]);
    const float2* a_r1 = reinterpret_cast<const float2*>(&g_Atab[(ra + 1) * 64]);
    const float2* b_r0 = reinterpret_cast<const float2*>(&g_Atab[rb * 64]);
    const float2* b_r1 = reinterpret_cast<const float2*>(&g_Atab[(rb + 1) * 64]);

    float xca = fminf(fmaxf(x2a, EPSF), 1.0f - EPSF);
    float xcb = fminf(fmaxf(x2b, EPSF), 1.0f - EPSF);
    float ta = 1.0f, tb = 1.0f;
    float Sa = 0.0f, Sb = 0.0f;
    const float inv = 1.0f / (float)NCELL;
    const float INF = __int_as_float(0x7f800000);

#pragma unroll 1
    for (int it = 0; it < NCELL + 2; it++) {
        int ca = max(0, min((int)(xca * (float)NCELL), NCELL - 1));
        float2 pa0 = __ldg(&a_r0[ca]);
        float2 pa1 = __ldg(&a_r1[ca]);
        int cb = max(0, min((int)(xcb * (float)NCELL), NCELL - 1));
        float2 pb0 = __ldg(&b_r0[cb]);
        float2 pb1 = __ldg(&b_r1[cb]);

        float aa = fmaf(fra, pa1.x - pa0.x, pa0.x);
        float ba = fmaf(fra, pa1.y - pa0.y, pa0.y);
        float ab = fmaf(frb, pb1.x - pb0.x, pb0.x);
        float bb = fmaf(frb, pb1.y - pb0.y, pb0.y);

        float va = aa * xca + ba;
        float vb = ab * xcb + bb;
        float xbnda = ((va >= 0.f) ? (float)(ca + 1) : (float)ca) * inv;
        float xbndb = ((vb >= 0.f) ? (float)(cb + 1) : (float)cb) * inv;
        bool sma = fabsf(aa) < TINYF;
        bool smb = fabsf(ab) < TINYF;
        float safa = sma ? 1.0f : aa;
        float safb = smb ? 1.0f : ab;
        float ea = ba / safa;
        float eb = bb / safb;
        float dena = xca + ea, denb = xcb + eb;
        float sdena = (fabsf(dena) < TINYF) ? ((dena >= 0.f) ? TINYF : -TINYF) : dena;
        float sdenb = (fabsf(denb) < TINYF) ? ((denb >= 0.f) ? TINYF : -TINYF) : denb;
        float rata = __fdividef(xbnda + ea, sdena);
        float ratb = __fdividef(xbndb + eb, sdenb);
        float thea = __fdividef(__logf(fmaxf(rata, TINYF)), safa);
        float theb = __fdividef(__logf(fmaxf(ratb, TINYF)), safb);
        float sba = (fabsf(ba) < TINYF) ? TINYF : ba;
        float sbb = (fabsf(bb) < TINYF) ? TINYF : bb;
        float thla = __fdividef(xbnda - xca, sba);
        float thlb = __fdividef(xbndb - xcb, sbb);
        float tha = sma ? thla : ((rata > TINYF) ? thea : INF);
        float thb = smb ? thlb : ((ratb > TINYF) ? theb : INF);
        tha = (tha <= 0.f) ? INF : tha;
        thb = (thb <= 0.f) ? INF : thb;
        float dta = fminf(tha, ta), dtb = fminf(thb, tb);
        bool cra = (tha <= ta), crb = (thb <= tb);
        float xea = (xca + ea) * __expf(aa * dta) - ea;
        float xeb = (xcb + eb) * __expf(ab * dtb) - eb;
        float xla = xca + ba * dta, xlb = xcb + bb * dtb;
        float xna = sma ? xla : xea;
        float xnb = smb ? xlb : xeb;
        float nga = (va >= 0.f) ? 1e-7f : -1e-7f;
        float ngb = (vb >= 0.f) ? 1e-7f : -1e-7f;
        xna = cra ? (xbnda + nga) : xna;
        xnb = crb ? (xbndb + ngb) : xnb;
        xna = fminf(fmaxf(xna, EPSF), 1.0f - EPSF);
        xnb = fminf(fmaxf(xnb, EPSF), 1.0f - EPSF);
        Sa += aa * dta;  Sb += ab * dtb;
        ta -= dta;       tb -= dtb;
        bool done = (dta == 0.0f) && (xna == xca) &&
                    (dtb == 0.0f) && (xnb == xcb);
        xca = xna; xcb = xnb;
        if (__all_sync(0xffffffffu, done)) break;
    }

    if (v1) {
        float4 z; z.x = xca; z.y = x1a; z.z = xcb; z.w = x1b;
        *reinterpret_cast<float4*>(&out[2 * ip0]) = z;
        float4 g; g.x = Sa; g.y = 0.0f; g.z = Sb; g.w = 0.0f;
        *reinterpret_cast<float4*>(&out[2 * n + 2 * ip0]) = g;
    } else if (v0) {
        out[2 * ip0]     = xca;
        out[2 * ip0 + 1] = x1a;
        out[2 * n + 2 * ip0]     = Sa;
        out[2 * n + 2 * ip0 + 1] = 0.0f;
    }
}

// ============================================================================
static float s_Bhost[DTH * 64];   // persists across graph replays

extern "C" void kernel_launch(void* const* d_in, const int* in_sizes, int n_in,
                              void* d_out, int out_size)
{
    const float* x  = (const float*)d_in[0];
    const float* w0 = (const float*)d_in[1];
    const float* b0 = (const float*)d_in[2];
    const float* w1 = (const float*)d_in[3];
    const float* b1 = (const float*)d_in[4];
    const float* w2 = (const float*)d_in[5];
    const float* b2 = (const float*)d_in[6];
    const float* w3 = (const float*)d_in[7];
    const float* b3 = (const float*)d_in[8];
    float* out = (float*)d_out;

    int n = in_sizes[0] / 2;
    const int nrows = GTAB + 1;

    compute_basis_host(s_Bhost);    // input-independent, deterministic
    cudaMemcpyToSymbolAsync(g_Bmat, s_Bhost, sizeof(s_Bhost), 0,
                            cudaMemcpyHostToDevice, 0);

    k0u_part<<<KCH, 256>>>(w0, b0, w1);

    dim3 g1((nrows + 31) / 32, 4);
    kT1_h2tab<<<g1, 256>>>(b1, w2, b2, nrows);

    kT2_atab<<<(nrows + 31) / 32, 256>>>(w3, b3, nrows);

    int npairs = (n + 1) / 2;
    k3_integrate<<<(npairs + 255) / 256, 256>>>(x, out, n);
}